// round 6
// baseline (speedup 1.0000x reference)
#include <cuda_runtime.h>
#include <cstdint>

#define B_ 4
#define S_ 2048
#define E_ 1024
#define H_ 16
#define D_ 64
#define BS_ (B_*S_)
#define BHSD (B_*H_*S_*D_)
#define LOG2E 1.4426950408889634f

// Scratch (device globals — no allocations allowed)
__device__ __align__(16) float g_buf[3*(size_t)BHSD]; // Q|K|V rounded (Q pre-scaled)
__device__ __align__(16) float g_ctx[(size_t)BS_*H_*D_];
__device__ __align__(16) float g_xr[(size_t)BS_*E_];
__device__ __align__(16) float g_Wqr[H_*E_*D_];
__device__ __align__(16) float g_Wkr[H_*E_*D_];
__device__ __align__(16) float g_Wvr[H_*E_*D_];
__device__ __align__(16) float g_Wor[H_*D_*E_];

// ---------------------------------------------------------------------------
__device__ __forceinline__ float f2tff(float f) {
    unsigned u; asm("cvt.rna.tf32.f32 %0, %1;" : "=r"(u) : "f"(f));
    return __uint_as_float(u);
}
__device__ __forceinline__ void mma8(float* c, const unsigned* a, const unsigned* b) {
    asm volatile(
        "mma.sync.aligned.m16n8k8.row.col.f32.tf32.tf32.f32 "
        "{%0,%1,%2,%3}, {%4,%5,%6,%7}, {%8,%9}, {%0,%1,%2,%3};\n"
        : "+f"(c[0]), "+f"(c[1]), "+f"(c[2]), "+f"(c[3])
        : "r"(a[0]), "r"(a[1]), "r"(a[2]), "r"(a[3]), "r"(b[0]), "r"(b[1]));
}
__device__ __forceinline__ void cp16(uint32_t d, const float* s) {
    asm volatile("cp.async.cg.shared.global [%0], [%1], 16;\n" :: "r"(d), "l"(s));
}
__device__ __forceinline__ void cp_commit() { asm volatile("cp.async.commit_group;\n"); }
__device__ __forceinline__ void cp_wait0()  { asm volatile("cp.async.wait_group 0;\n" ::: "memory"); }

// ---------------------------------------------------------------------------
// prep: one launch, rounds all 5 arrays to tf32 (rna).
// ---------------------------------------------------------------------------
#define N4_X  (BS_*E_/4)
#define N4_W  (H_*E_*D_/4)
#define N4_TOT (N4_X + 4*N4_W)

__global__ void prep_kernel(const float4* __restrict__ x,
                            const float4* __restrict__ Wq, const float4* __restrict__ Wk,
                            const float4* __restrict__ Wv, const float4* __restrict__ Wo)
{
    int i = blockIdx.x * blockDim.x + threadIdx.x;
    int stride = gridDim.x * blockDim.x;
    for (; i < N4_TOT; i += stride) {
        const float4* src; float4* dst; int j;
        if (i < N4_X)               { src = x;  dst = (float4*)g_xr;  j = i; }
        else if (i < N4_X + N4_W)   { src = Wq; dst = (float4*)g_Wqr; j = i - N4_X; }
        else if (i < N4_X + 2*N4_W) { src = Wk; dst = (float4*)g_Wkr; j = i - N4_X - N4_W; }
        else if (i < N4_X + 3*N4_W) { src = Wv; dst = (float4*)g_Wvr; j = i - N4_X - 2*N4_W; }
        else                        { src = Wo; dst = (float4*)g_Wor; j = i - N4_X - 3*N4_W; }
        float4 v = src[j];
        float4 w;
        w.x = f2tff(v.x); w.y = f2tff(v.y); w.z = f2tff(v.z); w.w = f2tff(v.w);
        dst[j] = w;
    }
}

// ---------------------------------------------------------------------------
// GEMM skeleton: CTA tile 128x128, K-tile 32, 4-stage cp.async ring,
// 256 thr / 8 warps (warp tile 32x64), fragment-register double buffering.
// smem floats: A stages 4*4608 (stride 36) | B stages 4*4352 (stride 136)
// ---------------------------------------------------------------------------
#define GEMM_SMEM 143360
#define A_ST(s) ((s) * 4608)
#define B_ST(s) (18432 + (s) * 4352)

// fragment load: a[2][4] (two 16-row m-tiles) + b[8][2] (eight 8-col n-frags)
__device__ __forceinline__ void ldfr(const float* A, const float* Bt, int k8,
                                     int wm, int wn, int g, int t,
                                     unsigned a[2][4], unsigned b[8][2])
{
    #pragma unroll
    for (int mi = 0; mi < 2; mi++) {
        const int r = wm * 32 + mi * 16 + g;
        a[mi][0] = __float_as_uint(A[r * 36 + k8 + t]);
        a[mi][1] = __float_as_uint(A[(r + 8) * 36 + k8 + t]);
        a[mi][2] = __float_as_uint(A[r * 36 + k8 + t + 4]);
        a[mi][3] = __float_as_uint(A[(r + 8) * 36 + k8 + t + 4]);
    }
    #pragma unroll
    for (int f = 0; f < 8; f++) {
        const int nc = wn * 64 + f * 8 + g;
        b[f][0] = __float_as_uint(Bt[(k8 + t) * 136 + nc]);
        b[f][1] = __float_as_uint(Bt[(k8 + t + 4) * 136 + nc]);
    }
}
__device__ __forceinline__ void mma16(float c[2][8][4], unsigned a[2][4], unsigned b[8][2])
{
    #pragma unroll
    for (int f = 0; f < 8; f++) {
        mma8(c[0][f], a[0], b[f]);
        mma8(c[1][f], a[1], b[f]);
    }
}

// ---------------------------------------------------------------------------
// Kernel 1: fused QKV projection. grid (64, 24), 256 threads, 1 CTA/SM.
// ---------------------------------------------------------------------------
__global__ __launch_bounds__(256, 1) void qkv_kernel(
    const float* __restrict__ bq, const float* __restrict__ bk, const float* __restrict__ bv)
{
    extern __shared__ float sm[];
    const int tid  = threadIdx.x;
    const int m0   = blockIdx.x * 128;
    const int p0   = blockIdx.y * 2;
    const int lane = tid & 31, wid = tid >> 5;
    const int wm   = wid >> 1, wn = wid & 1;
    const int g    = lane >> 2, t = lane & 3;
    const uint32_t smb = (uint32_t)__cvta_generic_to_shared(sm);

    const float* aSrc[4]; uint32_t aDst[4];
    #pragma unroll
    for (int i = 0; i < 4; i++) {
        int lin = tid + i * 256, row = lin >> 3, c4 = lin & 7;
        aSrc[i] = g_xr + (size_t)(m0 + row) * E_ + c4 * 4;
        aDst[i] = smb + (uint32_t)(row * 36 + c4 * 4) * 4u;
    }
    const float* bSrc[4]; uint32_t bDst[4];
    #pragma unroll
    for (int i = 0; i < 4; i++) {
        int lin = tid + i * 256, row = lin >> 5, c4 = lin & 31, ncol = c4 * 4;
        int pb = p0 + (c4 >> 4), wv = pb >> 4, hh = pb & 15;
        const float* base = (wv == 0) ? g_Wqr : (wv == 1) ? g_Wkr : g_Wvr;
        bSrc[i] = base + (size_t)hh * E_ * D_ + row * D_ + (ncol & 63);
        bDst[i] = smb + (uint32_t)(B_ST(0) + row * 136 + ncol) * 4u;
    }

    // prologue: tiles 0..2 -> stages 0..2
    #pragma unroll
    for (int ss = 0; ss < 3; ss++) {
        #pragma unroll
        for (int i = 0; i < 4; i++) {
            cp16(aDst[i] + (uint32_t)A_ST(ss) * 4u, aSrc[i] + (size_t)ss * 32);
            cp16(bDst[i] + (uint32_t)(ss * 4352) * 4u, bSrc[i] + (size_t)ss * 32 * D_);
        }
        cp_commit();
    }

    float c[2][8][4];
    #pragma unroll
    for (int mi = 0; mi < 2; mi++)
        #pragma unroll
        for (int f = 0; f < 8; f++)
            #pragma unroll
            for (int r = 0; r < 4; r++) c[mi][f][r] = 0.f;

    for (int kt = 0; kt < 32; kt++) {
        if (kt < 30)       asm volatile("cp.async.wait_group 2;" ::: "memory");
        else if (kt == 30) asm volatile("cp.async.wait_group 1;" ::: "memory");
        else               cp_wait0();
        __syncthreads();
        if (kt + 3 < 32) {
            const int s = (kt + 3) & 3;
            #pragma unroll
            for (int i = 0; i < 4; i++) {
                cp16(aDst[i] + (uint32_t)A_ST(s) * 4u, aSrc[i] + (size_t)(kt + 3) * 32);
                cp16(bDst[i] + (uint32_t)(s * 4352) * 4u, bSrc[i] + (size_t)(kt + 3) * 32 * D_);
            }
            cp_commit();
        }
        const float* A  = sm + A_ST(kt & 3);
        const float* Bt = sm + B_ST(kt & 3);

        // software-pipelined fragment loop: LDS(ks+1) overlaps HMMA(ks)
        unsigned aF[2][2][4], bF[2][8][2];
        ldfr(A, Bt, 0, wm, wn, g, t, aF[0], bF[0]);
        #pragma unroll
        for (int ks = 0; ks < 4; ks++) {
            const int cur = ks & 1;
            if (ks < 3) ldfr(A, Bt, (ks + 1) * 8, wm, wn, g, t, aF[cur ^ 1], bF[cur ^ 1]);
            mma16(c, aF[cur], bF[cur]);
        }
    }

    // epilogue: bias + tf32-round (+0.125*log2e for Q) -> g_buf [B,H,S,D]
    const int p  = p0 + wn;
    const int wv = p >> 4, hh = p & 15;
    float* outb = g_buf + (size_t)wv * BHSD;
    const float* bb = ((wv == 0) ? bq : (wv == 1) ? bk : bv) + hh * D_;
    const float scl = (wv == 0) ? (0.125f * LOG2E) : 1.0f;

    #pragma unroll
    for (int mi = 0; mi < 2; mi++) {
        const int r0 = m0 + wm * 32 + mi * 16 + g;
        #pragma unroll
        for (int f = 0; f < 8; f++) {
            const int col = f * 8 + t * 2;
            const float b0v = bb[col], b1v = bb[col + 1];
            {
                int gr = r0;
                float2 v;
                v.x = f2tff((c[mi][f][0] + b0v) * scl);
                v.y = f2tff((c[mi][f][1] + b1v) * scl);
                *(float2*)(outb + (((size_t)(gr >> 11) * H_ + hh) * S_ + (gr & 2047)) * D_ + col) = v;
            }
            {
                int gr = r0 + 8;
                float2 v;
                v.x = f2tff((c[mi][f][2] + b0v) * scl);
                v.y = f2tff((c[mi][f][3] + b1v) * scl);
                *(float2*)(outb + (((size_t)(gr >> 11) * H_ + hh) * S_ + (gr & 2047)) * D_ + col) = v;
            }
        }
    }
}

// ---------------------------------------------------------------------------
// Kernel 3: output projection. grid (64, 8), 256 threads, 1 CTA/SM.
// ---------------------------------------------------------------------------
__global__ __launch_bounds__(256, 1) void oproj_kernel(
    const float* __restrict__ bo, float* __restrict__ out)
{
    extern __shared__ float sm[];
    const int tid  = threadIdx.x;
    const int m0   = blockIdx.x * 128;
    const int n0   = blockIdx.y * 128;
    const int lane = tid & 31, wid = tid >> 5;
    const int wm   = wid >> 1, wn = wid & 1;
    const int g    = lane >> 2, t = lane & 3;
    const uint32_t smb = (uint32_t)__cvta_generic_to_shared(sm);

    const float* aSrc[4]; uint32_t aDst[4];
    #pragma unroll
    for (int i = 0; i < 4; i++) {
        int lin = tid + i * 256, row = lin >> 3, c4 = lin & 7;
        aSrc[i] = g_ctx + (size_t)(m0 + row) * E_ + c4 * 4;
        aDst[i] = smb + (uint32_t)(row * 36 + c4 * 4) * 4u;
    }
    const float* bSrc[4]; uint32_t bDst[4];
    #pragma unroll
    for (int i = 0; i < 4; i++) {
        int lin = tid + i * 256, row = lin >> 5, c4 = lin & 31, ncol = c4 * 4;
        bSrc[i] = g_Wor + (size_t)row * E_ + n0 + ncol;
        bDst[i] = smb + (uint32_t)(B_ST(0) + row * 136 + ncol) * 4u;
    }

    #pragma unroll
    for (int ss = 0; ss < 3; ss++) {
        #pragma unroll
        for (int i = 0; i < 4; i++) {
            cp16(aDst[i] + (uint32_t)A_ST(ss) * 4u, aSrc[i] + (size_t)ss * 32);
            cp16(bDst[i] + (uint32_t)(ss * 4352) * 4u, bSrc[i] + (size_t)ss * 32 * E_);
        }
        cp_commit();
    }

    float c[2][8][4];
    #pragma unroll
    for (int mi = 0; mi < 2; mi++)
        #pragma unroll
        for (int f = 0; f < 8; f++)
            #pragma unroll
            for (int r = 0; r < 4; r++) c[mi][f][r] = 0.f;

    for (int kt = 0; kt < 32; kt++) {
        if (kt < 30)       asm volatile("cp.async.wait_group 2;" ::: "memory");
        else if (kt == 30) asm volatile("cp.async.wait_group 1;" ::: "memory");
        else               cp_wait0();
        __syncthreads();
        if (kt + 3 < 32) {
            const int s = (kt + 3) & 3;
            #pragma unroll
            for (int i = 0; i < 4; i++) {
                cp16(aDst[i] + (uint32_t)A_ST(s) * 4u, aSrc[i] + (size_t)(kt + 3) * 32);
                cp16(bDst[i] + (uint32_t)(s * 4352) * 4u, bSrc[i] + (size_t)(kt + 3) * 32 * E_);
            }
            cp_commit();
        }
        const float* A  = sm + A_ST(kt & 3);
        const float* Bt = sm + B_ST(kt & 3);

        unsigned aF[2][2][4], bF[2][8][2];
        ldfr(A, Bt, 0, wm, wn, g, t, aF[0], bF[0]);
        #pragma unroll
        for (int ks = 0; ks < 4; ks++) {
            const int cur = ks & 1;
            if (ks < 3) ldfr(A, Bt, (ks + 1) * 8, wm, wn, g, t, aF[cur ^ 1], bF[cur ^ 1]);
            mma16(c, aF[cur], bF[cur]);
        }
    }

    #pragma unroll
    for (int mi = 0; mi < 2; mi++) {
        const int r0 = m0 + wm * 32 + mi * 16 + g;
        #pragma unroll
        for (int f = 0; f < 8; f++) {
            const int col = n0 + wn * 64 + f * 8 + t * 2;
            const float b0v = bo[col], b1v = bo[col + 1];
            float2 v0; v0.x = c[mi][f][0] + b0v; v0.y = c[mi][f][1] + b1v;
            *(float2*)(out + (size_t)r0 * E_ + col) = v0;
            float2 v1; v1.x = c[mi][f][2] + b0v; v1.y = c[mi][f][3] + b1v;
            *(float2*)(out + (size_t)(r0 + 8) * E_ + col) = v1;
        }
    }
}

// ---------------------------------------------------------------------------
// Kernel 2: causal flash attention (unchanged passing r4 version).
// ---------------------------------------------------------------------------
#define FLASH_SMEM 106496

__global__ __launch_bounds__(256, 2) void flash_kernel()
{
    extern __shared__ float sm[];
    float* Ps = sm + 17920;

    const int iq = (int)(gridDim.x - 1 - blockIdx.x);
    const int h = blockIdx.y, b = blockIdx.z;
    const int q0 = iq * 128;
    const size_t head_base = ((size_t)b * H_ + h) * S_ * D_;
    const float* Qg = g_buf + head_base;
    const float* Kg = g_buf + BHSD + head_base;

    const int tid  = threadIdx.x;
    const int lane = tid & 31, wid = tid >> 5;
    const int g    = lane >> 2, t = lane & 3;
    const int qrow = wid * 16 + g;
    const uint32_t smb = (uint32_t)__cvta_generic_to_shared(sm);

    const float* kSrc[4]; uint32_t kDst[4], vDst[4];
    #pragma unroll
    for (int i = 0; i < 4; i++) {
        int lin = tid + i * 256, row = lin >> 4, c4 = lin & 15;
        kSrc[i] = Kg + (size_t)row * D_ + c4 * 4;
        kDst[i] = smb + (uint32_t)(row * 68 + c4 * 4) * 4u;
        vDst[i] = smb + (uint32_t)(8704 + row * 72 + c4 * 4) * 4u;
    }

    #pragma unroll
    for (int i = 0; i < 4; i++) { cp16(kDst[i], kSrc[i]); cp16(vDst[i], kSrc[i] + BHSD); }
    cp_commit();

    #pragma unroll
    for (int i = 0; i < 8; i++) {
        int lin = tid + i * 256, row = lin >> 4, c4 = lin & 15;
        *(float4*)&Ps[row * 68 + c4 * 4] =
            *(const float4*)(Qg + (size_t)(q0 + row) * D_ + c4 * 4);
    }
    __syncthreads();

    unsigned aQ[8][4];
    #pragma unroll
    for (int kk = 0; kk < 8; kk++) {
        const int d8 = kk * 8;
        aQ[kk][0] = __float_as_uint(Ps[qrow * 68 + d8 + t]);
        aQ[kk][1] = __float_as_uint(Ps[(qrow + 8) * 68 + d8 + t]);
        aQ[kk][2] = __float_as_uint(Ps[qrow * 68 + d8 + t + 4]);
        aQ[kk][3] = __float_as_uint(Ps[(qrow + 8) * 68 + d8 + t + 4]);
    }
    __syncthreads();

    float cO[8][4];
    #pragma unroll
    for (int f = 0; f < 8; f++)
        #pragma unroll
        for (int r = 0; r < 4; r++) cO[f][r] = 0.f;
    float m0_ = -1e30f, m1_ = -1e30f, l0_ = 0.f, l1_ = 0.f;

    const int jtmax = 2 * iq + 1;
    for (int jt = 0; jt <= jtmax; jt++) {
        cp_wait0();
        __syncthreads();
        const float* Kst = sm + (jt & 1) * 4352;
        const int k0 = jt * 64;

        float cS[8][4];
        #pragma unroll
        for (int f = 0; f < 8; f++)
            #pragma unroll
            for (int r = 0; r < 4; r++) cS[f][r] = 0.f;
        #pragma unroll
        for (int kk = 0; kk < 8; kk++) {
            const int d8 = kk * 8;
            #pragma unroll
            for (int f = 0; f < 8; f++) {
                unsigned bfr[2];
                bfr[0] = __float_as_uint(Kst[(f * 8 + g) * 68 + d8 + t]);
                bfr[1] = __float_as_uint(Kst[(f * 8 + g) * 68 + d8 + t + 4]);
                mma8(cS[f], aQ[kk], bfr);
            }
        }

        if (jt > 0) {
            const float* Vprev = sm + 8704 + ((jt - 1) & 1) * 4608;
            #pragma unroll
            for (int kk = 0; kk < 8; kk++) {
                const int s8 = kk * 8;
                unsigned a[4];
                a[0] = __float_as_uint(Ps[qrow * 68 + s8 + t]);
                a[1] = __float_as_uint(Ps[(qrow + 8) * 68 + s8 + t]);
                a[2] = __float_as_uint(Ps[qrow * 68 + s8 + t + 4]);
                a[3] = __float_as_uint(Ps[(qrow + 8) * 68 + s8 + t + 4]);
                #pragma unroll
                for (int f = 0; f < 8; f++) {
                    unsigned bfr[2];
                    bfr[0] = __float_as_uint(Vprev[(s8 + t) * 72 + f * 8 + g]);
                    bfr[1] = __float_as_uint(Vprev[(s8 + t + 4) * 72 + f * 8 + g]);
                    mma8(cO[f], a, bfr);
                }
            }
        }
        __syncthreads();

        if (jt < jtmax) {
            const uint32_t st = ((jt + 1) & 1);
            #pragma unroll
            for (int i = 0; i < 4; i++) {
                cp16(kDst[i] + st * 17408u, kSrc[i] + (size_t)(jt + 1) * 4096);
                cp16(vDst[i] + st * 18432u, kSrc[i] + BHSD + (size_t)(jt + 1) * 4096);
            }
            cp_commit();
        }

        if (jt >= 2 * iq) {
            const int r0 = q0 + qrow, r1 = r0 + 8;
            #pragma unroll
            for (int f = 0; f < 8; f++) {
                const int col = k0 + f * 8 + t * 2;
                if (col     > r0) cS[f][0] = -1e30f;
                if (col + 1 > r0) cS[f][1] = -1e30f;
                if (col     > r1) cS[f][2] = -1e30f;
                if (col + 1 > r1) cS[f][3] = -1e30f;
            }
        }

        float rm0 = -1e30f, rm1 = -1e30f;
        #pragma unroll
        for (int f = 0; f < 8; f++) {
            rm0 = fmaxf(rm0, fmaxf(cS[f][0], cS[f][1]));
            rm1 = fmaxf(rm1, fmaxf(cS[f][2], cS[f][3]));
        }
        rm0 = fmaxf(rm0, __shfl_xor_sync(0xffffffffu, rm0, 1));
        rm0 = fmaxf(rm0, __shfl_xor_sync(0xffffffffu, rm0, 2));
        rm1 = fmaxf(rm1, __shfl_xor_sync(0xffffffffu, rm1, 1));
        rm1 = fmaxf(rm1, __shfl_xor_sync(0xffffffffu, rm1, 2));

        const float nm0 = fmaxf(m0_, rm0);
        const float nm1 = fmaxf(m1_, rm1);
        const float corr0 = exp2f(m0_ - nm0);
        const float corr1 = exp2f(m1_ - nm1);
        m0_ = nm0; m1_ = nm1;

        float rs0 = 0.f, rs1 = 0.f;
        #pragma unroll
        for (int f = 0; f < 8; f++) {
            float p0v = exp2f(cS[f][0] - nm0);
            float p1v = exp2f(cS[f][1] - nm0);
            float p2v = exp2f(cS[f][2] - nm1);
            float p3v = exp2f(cS[f][3] - nm1);
            rs0 += p0v + p1v;
            rs1 += p2v + p3v;
            float2 v0; v0.x = f2tff(p0v); v0.y = f2tff(p1v);
            *(float2*)&Ps[qrow * 68 + f * 8 + t * 2] = v0;
            float2 v1; v1.x = f2tff(p2v); v1.y = f2tff(p3v);
            *(float2*)&Ps[(qrow + 8) * 68 + f * 8 + t * 2] = v1;
        }
        rs0 += __shfl_xor_sync(0xffffffffu, rs0, 1);
        rs0 += __shfl_xor_sync(0xffffffffu, rs0, 2);
        rs1 += __shfl_xor_sync(0xffffffffu, rs1, 1);
        rs1 += __shfl_xor_sync(0xffffffffu, rs1, 2);
        l0_ = l0_ * corr0 + rs0;
        l1_ = l1_ * corr1 + rs1;
        #pragma unroll
        for (int f = 0; f < 8; f++) {
            cO[f][0] *= corr0; cO[f][1] *= corr0;
            cO[f][2] *= corr1; cO[f][3] *= corr1;
        }
        __syncwarp();
    }

    {
        const float* Vlast = sm + 8704 + (jtmax & 1) * 4608;
        #pragma unroll
        for (int kk = 0; kk < 8; kk++) {
            const int s8 = kk * 8;
            unsigned a[4];
            a[0] = __float_as_uint(Ps[qrow * 68 + s8 + t]);
            a[1] = __float_as_uint(Ps[(qrow + 8) * 68 + s8 + t]);
            a[2] = __float_as_uint(Ps[qrow * 68 + s8 + t + 4]);
            a[3] = __float_as_uint(Ps[(qrow + 8) * 68 + s8 + t + 4]);
            #pragma unroll
            for (int f = 0; f < 8; f++) {
                unsigned bfr[2];
                bfr[0] = __float_as_uint(Vlast[(s8 + t) * 72 + f * 8 + g]);
                bfr[1] = __float_as_uint(Vlast[(s8 + t + 4) * 72 + f * 8 + g]);
                mma8(cO[f], a, bfr);
            }
        }
    }

    const float inv0 = 1.0f / l0_;
    const float inv1 = 1.0f / l1_;
    const int q_a = q0 + qrow, q_b = q_a + 8;
    #pragma unroll
    for (int f = 0; f < 8; f++) {
        const int col = f * 8 + t * 2;
        float2 v0; v0.x = f2tff(cO[f][0] * inv0); v0.y = f2tff(cO[f][1] * inv0);
        *(float2*)(g_ctx + (((size_t)b * S_ + q_a) * H_ + h) * D_ + col) = v0;
        float2 v1; v1.x = f2tff(cO[f][2] * inv1); v1.y = f2tff(cO[f][3] * inv1);
        *(float2*)(g_ctx + (((size_t)b * S_ + q_b) * H_ + h) * D_ + col) = v1;
    }
}

// ---------------------------------------------------------------------------
extern "C" void kernel_launch(void* const* d_in, const int* in_sizes, int n_in,
                              void* d_out, int out_size)
{
    const float* x  = (const float*)d_in[0];
    const float* Wq = (const float*)d_in[1];
    const float* Wk = (const float*)d_in[2];
    const float* Wv = (const float*)d_in[3];
    const float* bq = (const float*)d_in[4];
    const float* bk = (const float*)d_in[5];
    const float* bv = (const float*)d_in[6];
    const float* Wo = (const float*)d_in[7];
    const float* bo = (const float*)d_in[8];
    float* out = (float*)d_out;

    cudaFuncSetAttribute(qkv_kernel,   cudaFuncAttributeMaxDynamicSharedMemorySize, GEMM_SMEM);
    cudaFuncSetAttribute(flash_kernel, cudaFuncAttributeMaxDynamicSharedMemorySize, FLASH_SMEM);
    cudaFuncSetAttribute(oproj_kernel, cudaFuncAttributeMaxDynamicSharedMemorySize, GEMM_SMEM);

    prep_kernel<<<2368, 256>>>((const float4*)x, (const float4*)Wq,
                               (const float4*)Wk, (const float4*)Wv, (const float4*)Wo);
    qkv_kernel<<<dim3(BS_ / 128, 24), 256, GEMM_SMEM>>>(bq, bk, bv);
    flash_kernel<<<dim3(S_ / 128, H_, B_), 256, FLASH_SMEM>>>();
    oproj_kernel<<<dim3(BS_ / 128, E_ / 128), 256, GEMM_SMEM>>>(bo, out);
}

// round 7
// speedup vs baseline: 1.8220x; 1.8220x over previous
#include <cuda_runtime.h>
#include <cuda_fp16.h>
#include <cstdint>

#define B_ 4
#define S_ 2048
#define E_ 1024
#define H_ 16
#define D_ 64
#define BS_ (B_*S_)
#define BHSD (B_*H_*S_*D_)
#define LOG2E 1.4426950408889634f

// Scratch (device globals — no allocations allowed). All fp16.
__device__ __align__(16) __half g_qh[(size_t)BHSD];        // [b,h][s][d], pre-scaled
__device__ __align__(16) __half g_kh[(size_t)BHSD];        // [b,h][s][d]
__device__ __align__(16) __half g_vh[(size_t)BHSD];        // [b,h][d][s]  (transposed!)
__device__ __align__(16) __half g_ctxh[(size_t)BS_*E_];    // [s][h*d]
__device__ __align__(16) __half g_xh[(size_t)BS_*E_];      // [s][e]
__device__ __align__(16) __half g_Wqh[H_*E_*D_];           // [h][d][e]
__device__ __align__(16) __half g_Wkh[H_*E_*D_];           // [h][d][e]
__device__ __align__(16) __half g_Wvh[H_*E_*D_];           // [h][d][e]
__device__ __align__(16) __half g_Woh[H_*D_*E_];           // [n][k]

// ---------------------------------------------------------------------------
__device__ __forceinline__ unsigned pack2h(float a, float b) {
    __half2 h = __floats2half2_rn(a, b);
    return *(unsigned*)&h;
}
__device__ __forceinline__ void mma_h(float* c, const unsigned* a, const unsigned* b) {
    asm volatile(
        "mma.sync.aligned.m16n8k16.row.col.f32.f16.f16.f32 "
        "{%0,%1,%2,%3}, {%4,%5,%6,%7}, {%8,%9}, {%0,%1,%2,%3};\n"
        : "+f"(c[0]), "+f"(c[1]), "+f"(c[2]), "+f"(c[3])
        : "r"(a[0]), "r"(a[1]), "r"(a[2]), "r"(a[3]), "r"(b[0]), "r"(b[1]));
}
__device__ __forceinline__ void cp16(uint32_t d, const __half* s) {
    asm volatile("cp.async.cg.shared.global [%0], [%1], 16;\n" :: "r"(d), "l"(s));
}
__device__ __forceinline__ void cp_commit() { asm volatile("cp.async.commit_group;\n"); }
__device__ __forceinline__ void cp_wait0()  { asm volatile("cp.async.wait_group 0;\n" ::: "memory"); }

// ---------------------------------------------------------------------------
// prep: fp16-convert x; transpose+convert Wq/Wk/Wv -> [h][d][e]; Wo -> [n][k]
// ---------------------------------------------------------------------------
#define N4_X  (BS_*E_/4)
#define N4_W  (H_*E_*D_/4)
#define N4_TOT (N4_X + 4*N4_W)

__global__ void prep_kernel(const float* __restrict__ x,
                            const float* __restrict__ Wq, const float* __restrict__ Wk,
                            const float* __restrict__ Wv, const float* __restrict__ Wo)
{
    int i = blockIdx.x * blockDim.x + threadIdx.x;
    int stride = gridDim.x * blockDim.x;
    for (; i < N4_TOT; i += stride) {
        if (i < N4_X) {
            float4 v = ((const float4*)x)[i];
            ((uint2*)g_xh)[i] = make_uint2(pack2h(v.x, v.y), pack2h(v.z, v.w));
        } else if (i < N4_X + 3 * N4_W) {
            int tt = i - N4_X;
            int wsel = tt / N4_W, o4 = tt % N4_W;
            const float* W = (wsel == 0) ? Wq : (wsel == 1) ? Wk : Wv;
            __half* dst = (wsel == 0) ? g_Wqh : (wsel == 1) ? g_Wkh : g_Wvh;
            int o = o4 * 4;
            int e = o & (E_ - 1);
            int rest = o >> 10;
            int d = rest & (D_ - 1);
            int hh = rest >> 6;
            const float* src = W + (size_t)hh * E_ * D_ + d;
            float v0 = src[(size_t)(e + 0) * D_];
            float v1 = src[(size_t)(e + 1) * D_];
            float v2 = src[(size_t)(e + 2) * D_];
            float v3 = src[(size_t)(e + 3) * D_];
            ((uint2*)dst)[o4] = make_uint2(pack2h(v0, v1), pack2h(v2, v3));
        } else {
            int o4 = i - N4_X - 3 * N4_W;
            int o = o4 * 4;
            int k = o & 1023;
            int n = o >> 10;
            float v0 = Wo[(size_t)(k + 0) * E_ + n];
            float v1 = Wo[(size_t)(k + 1) * E_ + n];
            float v2 = Wo[(size_t)(k + 2) * E_ + n];
            float v3 = Wo[(size_t)(k + 3) * E_ + n];
            ((uint2*)g_Woh)[o4] = make_uint2(pack2h(v0, v1), pack2h(v2, v3));
        }
    }
}

// ---------------------------------------------------------------------------
// GEMM skeleton (fp16 m16n8k16): CTA tile 128x128, K-tile 32, 3-stage ring,
// 256 thr / 8 warps (wm 0..3 x wn 0..1, warp tile 32x64).
// smem rows padded to 40 halves (80B): bank-conflict-free fragments.
// A stage 128*80=10240B, B stage 10240B. Total 61440B.
// ---------------------------------------------------------------------------
#define GEMM_SMEM 61440
#define A_STB(s) ((uint32_t)(s) * 10240u)
#define B_STB(s) (30720u + (uint32_t)(s) * 10240u)

__device__ __forceinline__ void gemm_tile(float c[2][8][4], const char* smc, int stage,
                                          int wm, int wn, int g, int t)
{
    const unsigned* Aw = (const unsigned*)(smc + A_STB(stage));
    const unsigned* Bw = (const unsigned*)(smc + B_STB(stage));
    #pragma unroll
    for (int ks = 0; ks < 2; ks++) {
        const int k8 = ks * 8 + t;
        unsigned a[2][4];
        #pragma unroll
        for (int mi = 0; mi < 2; mi++) {
            const int base = (wm * 32 + mi * 16 + g) * 20 + k8;
            a[mi][0] = Aw[base];
            a[mi][1] = Aw[base + 160];
            a[mi][2] = Aw[base + 4];
            a[mi][3] = Aw[base + 164];
        }
        #pragma unroll
        for (int f = 0; f < 8; f++) {
            const int w = (wn * 64 + f * 8 + g) * 20 + k8;
            unsigned b[2] = { Bw[w], Bw[w + 4] };
            mma_h(c[0][f], a[0], b);
            mma_h(c[1][f], a[1], b);
        }
    }
}

// ---------------------------------------------------------------------------
// Kernel 1: fused QKV projection. grid (64, 24), 256 threads, 2 CTA/SM.
// ---------------------------------------------------------------------------
__global__ __launch_bounds__(256, 2) void qkv_kernel(
    const float* __restrict__ bq, const float* __restrict__ bk, const float* __restrict__ bv)
{
    extern __shared__ char smc[];
    const int tid  = threadIdx.x;
    const int m0   = blockIdx.x * 128;
    const int p0   = blockIdx.y * 2;
    const int lane = tid & 31, wid = tid >> 5;
    const int wm   = wid >> 1, wn = wid & 1;
    const int g    = lane >> 2, t = lane & 3;
    const uint32_t smb = (uint32_t)__cvta_generic_to_shared(smc);

    // 512 A-chunks + 512 B-chunks of 16B; 2 each per thread
    const __half* aS[2]; uint32_t aO[2];
    const __half* bS[2]; uint32_t bO[2];
    #pragma unroll
    for (int i = 0; i < 2; i++) {
        int c = tid + i * 256;
        int row = c >> 2, cpos = c & 3;
        aS[i] = g_xh + (size_t)(m0 + row) * E_ + cpos * 8;
        aO[i] = (uint32_t)(row * 80 + cpos * 16);
        int p = p0 + (row >> 6), op = p >> 4, hh = p & 15, d = row & 63;
        const __half* base = (op == 0) ? g_Wqh : (op == 1) ? g_Wkh : g_Wvh;
        bS[i] = base + ((size_t)hh * D_ + d) * E_ + cpos * 8;
        bO[i] = aO[i];
    }

    // prologue: tiles 0,1 -> stages 0,1
    #pragma unroll
    for (int ss = 0; ss < 2; ss++) {
        #pragma unroll
        for (int i = 0; i < 2; i++) {
            cp16(smb + A_STB(ss) + aO[i], aS[i] + ss * 32);
            cp16(smb + B_STB(ss) + bO[i], bS[i] + ss * 32);
        }
        cp_commit();
    }

    float c[2][8][4];
    #pragma unroll
    for (int mi = 0; mi < 2; mi++)
        #pragma unroll
        for (int f = 0; f < 8; f++)
            #pragma unroll
            for (int r = 0; r < 4; r++) c[mi][f][r] = 0.f;

    for (int kt = 0; kt < 32; kt++) {
        if (kt < 31) asm volatile("cp.async.wait_group 1;" ::: "memory");
        else         cp_wait0();
        __syncthreads();
        if (kt + 2 < 32) {
            const int s = (kt + 2) % 3;
            #pragma unroll
            for (int i = 0; i < 2; i++) {
                cp16(smb + A_STB(s) + aO[i], aS[i] + (size_t)(kt + 2) * 32);
                cp16(smb + B_STB(s) + bO[i], bS[i] + (size_t)(kt + 2) * 32);
            }
            cp_commit();
        }
        gemm_tile(c, smc, kt % 3, wm, wn, g, t);
    }

    // epilogue: bias, scale Q, fp16-round, store
    const int p  = p0 + wn;
    const int op = p >> 4, hh = p & 15;
    const float* bb = ((op == 0) ? bq : (op == 1) ? bk : bv) + hh * D_;

    #pragma unroll
    for (int mi = 0; mi < 2; mi++) {
        #pragma unroll
        for (int rr = 0; rr < 2; rr++) {
            const int gr = m0 + wm * 32 + mi * 16 + g + rr * 8;
            const int bbi = gr >> 11, ssi = gr & 2047;
            #pragma unroll
            for (int f = 0; f < 8; f++) {
                const int col = f * 8 + t * 2;
                float v0 = c[mi][f][rr * 2 + 0] + bb[col];
                float v1 = c[mi][f][rr * 2 + 1] + bb[col + 1];
                if (op == 0) {
                    v0 *= 0.125f * LOG2E; v1 *= 0.125f * LOG2E;
                    *(unsigned*)(g_qh + (((size_t)bbi * H_ + hh) * S_ + ssi) * D_ + col) = pack2h(v0, v1);
                } else if (op == 1) {
                    *(unsigned*)(g_kh + (((size_t)bbi * H_ + hh) * S_ + ssi) * D_ + col) = pack2h(v0, v1);
                } else {
                    // V transposed: [b,h][d][s]
                    __half* vb = g_vh + ((size_t)bbi * H_ + hh) * D_ * S_ + ssi;
                    vb[(size_t)col * S_]       = __float2half_rn(v0);
                    vb[(size_t)(col + 1) * S_] = __float2half_rn(v1);
                }
            }
        }
    }
}

// ---------------------------------------------------------------------------
// Kernel 3: output projection. grid (64, 8), 256 threads, 2 CTA/SM.
// ---------------------------------------------------------------------------
__global__ __launch_bounds__(256, 2) void oproj_kernel(
    const float* __restrict__ bo, float* __restrict__ out)
{
    extern __shared__ char smc[];
    const int tid  = threadIdx.x;
    const int m0   = blockIdx.x * 128;
    const int n0   = blockIdx.y * 128;
    const int lane = tid & 31, wid = tid >> 5;
    const int wm   = wid >> 1, wn = wid & 1;
    const int g    = lane >> 2, t = lane & 3;
    const uint32_t smb = (uint32_t)__cvta_generic_to_shared(smc);

    const __half* aS[2]; uint32_t aO[2];
    const __half* bS[2];
    #pragma unroll
    for (int i = 0; i < 2; i++) {
        int c = tid + i * 256;
        int row = c >> 2, cpos = c & 3;
        aS[i] = g_ctxh + (size_t)(m0 + row) * E_ + cpos * 8;
        aO[i] = (uint32_t)(row * 80 + cpos * 16);
        bS[i] = g_Woh + (size_t)(n0 + row) * E_ + cpos * 8;
    }

    #pragma unroll
    for (int ss = 0; ss < 2; ss++) {
        #pragma unroll
        for (int i = 0; i < 2; i++) {
            cp16(smb + A_STB(ss) + aO[i], aS[i] + ss * 32);
            cp16(smb + B_STB(ss) + aO[i], bS[i] + ss * 32);
        }
        cp_commit();
    }

    float c[2][8][4];
    #pragma unroll
    for (int mi = 0; mi < 2; mi++)
        #pragma unroll
        for (int f = 0; f < 8; f++)
            #pragma unroll
            for (int r = 0; r < 4; r++) c[mi][f][r] = 0.f;

    for (int kt = 0; kt < 32; kt++) {
        if (kt < 31) asm volatile("cp.async.wait_group 1;" ::: "memory");
        else         cp_wait0();
        __syncthreads();
        if (kt + 2 < 32) {
            const int s = (kt + 2) % 3;
            #pragma unroll
            for (int i = 0; i < 2; i++) {
                cp16(smb + A_STB(s) + aO[i], aS[i] + (size_t)(kt + 2) * 32);
                cp16(smb + B_STB(s) + aO[i], bS[i] + (size_t)(kt + 2) * 32);
            }
            cp_commit();
        }
        gemm_tile(c, smc, kt % 3, wm, wn, g, t);
    }

    #pragma unroll
    for (int mi = 0; mi < 2; mi++) {
        const int r0 = m0 + wm * 32 + mi * 16 + g;
        #pragma unroll
        for (int f = 0; f < 8; f++) {
            const int col = n0 + wn * 64 + f * 8 + t * 2;
            const float b0v = bo[col], b1v = bo[col + 1];
            float2 v0; v0.x = c[mi][f][0] + b0v; v0.y = c[mi][f][1] + b1v;
            *(float2*)(out + (size_t)r0 * E_ + col) = v0;
            float2 v1; v1.x = c[mi][f][2] + b0v; v1.y = c[mi][f][3] + b1v;
            *(float2*)(out + (size_t)(r0 + 8) * E_ + col) = v1;
        }
    }
}

// ---------------------------------------------------------------------------
// Kernel 2: causal flash attention, fp16 m16n8k16.
// Block = 128 queries of one (b,h), Bkv=64, 256 thr / 8 warps, 2 CTA/SM.
// smem (bytes): Q[128][72h]@0 (18432) | K 2x[64][72h]@18432 | Vt 2x[64][72h]@36864
//               | P[128][72h]@55296.  Total 73728.
// ---------------------------------------------------------------------------
#define FLASH_SMEM 73728
#define FK_STB(s) (18432u + (uint32_t)(s) * 9216u)
#define FV_STB(s) (36864u + (uint32_t)(s) * 9216u)
#define FP_OFFB   55296u

__global__ __launch_bounds__(256, 2) void flash_kernel()
{
    extern __shared__ char smc[];
    const uint32_t smb = (uint32_t)__cvta_generic_to_shared(smc);
    const unsigned* Qw = (const unsigned*)smc;
    unsigned* Pw = (unsigned*)(smc + FP_OFFB);

    const int iq = (int)(gridDim.x - 1 - blockIdx.x);   // heavy-first
    const int h = blockIdx.y, b = blockIdx.z;
    const int q0 = iq * 128;
    const size_t head = ((size_t)b * H_ + h) * S_ * D_; // same value for [s][d] and [d][s]
    const __half* Qg = g_qh + head;
    const __half* Kg = g_kh + head;
    const __half* Vg = g_vh + head;

    const int tid  = threadIdx.x;
    const int lane = tid & 31, wid = tid >> 5;
    const int g    = lane >> 2, t = lane & 3;
    const int qrow = wid * 16 + g;

    const __half* kS[2]; const __half* vS[2]; uint32_t kO[2];
    #pragma unroll
    for (int i = 0; i < 2; i++) {
        int c = tid + i * 256;
        int row = c >> 3, cpos = c & 7;
        kS[i] = Kg + (size_t)row * D_ + cpos * 8;
        vS[i] = Vg + (size_t)row * S_ + cpos * 8;   // Vt row = d, cols = keys
        kO[i] = (uint32_t)(row * 144 + cpos * 16);
    }

    // prologue: Q (1024 chunks) + K/V tile 0, one group
    #pragma unroll
    for (int i = 0; i < 4; i++) {
        int c = tid + i * 256;
        int row = c >> 3, cpos = c & 7;
        cp16(smb + (uint32_t)(row * 144 + cpos * 16), Qg + (size_t)(q0 + row) * D_ + cpos * 8);
    }
    #pragma unroll
    for (int i = 0; i < 2; i++) {
        cp16(smb + FK_STB(0) + kO[i], kS[i]);
        cp16(smb + FV_STB(0) + kO[i], vS[i]);
    }
    cp_commit();
    cp_wait0();
    __syncthreads();

    // Q fragments to registers (warp-private rows)
    unsigned aQ[4][4];
    #pragma unroll
    for (int kk = 0; kk < 4; kk++) {
        const int base = qrow * 36 + kk * 8 + t;
        aQ[kk][0] = Qw[base];
        aQ[kk][1] = Qw[base + 288];
        aQ[kk][2] = Qw[base + 4];
        aQ[kk][3] = Qw[base + 292];
    }

    float cO[8][4];
    #pragma unroll
    for (int f = 0; f < 8; f++)
        #pragma unroll
        for (int r = 0; r < 4; r++) cO[f][r] = 0.f;
    float m0_ = -1e30f, m1_ = -1e30f, l0_ = 0.f, l1_ = 0.f;

    const int jtmax = 2 * iq + 1;
    for (int jt = 0; jt <= jtmax; jt++) {
        if (jt > 0) {
            cp_wait0();
            __syncthreads();
        }
        if (jt < jtmax) {
            const uint32_t st = (uint32_t)((jt + 1) & 1);
            #pragma unroll
            for (int i = 0; i < 2; i++) {
                cp16(smb + FK_STB(st) + kO[i], kS[i] + (size_t)(jt + 1) * 4096);
                cp16(smb + FV_STB(st) + kO[i], vS[i] + (size_t)(jt + 1) * 64);
            }
            cp_commit();
        }
        const unsigned* Kw = (const unsigned*)(smc + FK_STB(jt & 1));
        const unsigned* Vw = (const unsigned*)(smc + FV_STB(jt & 1));
        const int k0 = jt * 64;

        // S = Q K^T
        float cS[8][4];
        #pragma unroll
        for (int f = 0; f < 8; f++)
            #pragma unroll
            for (int r = 0; r < 4; r++) cS[f][r] = 0.f;
        #pragma unroll
        for (int kk = 0; kk < 4; kk++) {
            #pragma unroll
            for (int f = 0; f < 8; f++) {
                const int w = (f * 8 + g) * 36 + kk * 8 + t;
                unsigned bfr[2] = { Kw[w], Kw[w + 4] };
                mma_h(cS[f], aQ[kk], bfr);
            }
        }

        // causal mask (diagonal-crossing tiles only)
        if (jt >= 2 * iq) {
            const int r0 = q0 + qrow, r1 = r0 + 8;
            #pragma unroll
            for (int f = 0; f < 8; f++) {
                const int col = k0 + f * 8 + t * 2;
                if (col     > r0) cS[f][0] = -1e30f;
                if (col + 1 > r0) cS[f][1] = -1e30f;
                if (col     > r1) cS[f][2] = -1e30f;
                if (col + 1 > r1) cS[f][3] = -1e30f;
            }
        }

        // online softmax (exp2 domain; Q pre-scaled by 0.125*log2e)
        float rm0 = -1e30f, rm1 = -1e30f;
        #pragma unroll
        for (int f = 0; f < 8; f++) {
            rm0 = fmaxf(rm0, fmaxf(cS[f][0], cS[f][1]));
            rm1 = fmaxf(rm1, fmaxf(cS[f][2], cS[f][3]));
        }
        rm0 = fmaxf(rm0, __shfl_xor_sync(0xffffffffu, rm0, 1));
        rm0 = fmaxf(rm0, __shfl_xor_sync(0xffffffffu, rm0, 2));
        rm1 = fmaxf(rm1, __shfl_xor_sync(0xffffffffu, rm1, 1));
        rm1 = fmaxf(rm1, __shfl_xor_sync(0xffffffffu, rm1, 2));

        const float nm0 = fmaxf(m0_, rm0);
        const float nm1 = fmaxf(m1_, rm1);
        const float corr0 = exp2f(m0_ - nm0);
        const float corr1 = exp2f(m1_ - nm1);
        m0_ = nm0; m1_ = nm1;

        float rs0 = 0.f, rs1 = 0.f;
        #pragma unroll
        for (int f = 0; f < 8; f++) {
            float p0v = exp2f(cS[f][0] - nm0);
            float p1v = exp2f(cS[f][1] - nm0);
            float p2v = exp2f(cS[f][2] - nm1);
            float p3v = exp2f(cS[f][3] - nm1);
            rs0 += p0v + p1v;
            rs1 += p2v + p3v;
            const int w = qrow * 36 + f * 4 + t;
            Pw[w]       = pack2h(p0v, p1v);
            Pw[w + 288] = pack2h(p2v, p3v);
        }
        rs0 += __shfl_xor_sync(0xffffffffu, rs0, 1);
        rs0 += __shfl_xor_sync(0xffffffffu, rs0, 2);
        rs1 += __shfl_xor_sync(0xffffffffu, rs1, 1);
        rs1 += __shfl_xor_sync(0xffffffffu, rs1, 2);
        l0_ = l0_ * corr0 + rs0;
        l1_ = l1_ * corr1 + rs1;
        #pragma unroll
        for (int f = 0; f < 8; f++) {
            cO[f][0] *= corr0; cO[f][1] *= corr0;
            cO[f][2] *= corr1; cO[f][3] *= corr1;
        }
        __syncwarp();

        // O += P V  (A = P warp-private rows; B = V^T [d][key], key-contig)
        #pragma unroll
        for (int kk = 0; kk < 4; kk++) {
            const int base = qrow * 36 + kk * 8 + t;
            unsigned a[4];
            a[0] = Pw[base];
            a[1] = Pw[base + 288];
            a[2] = Pw[base + 4];
            a[3] = Pw[base + 292];
            #pragma unroll
            for (int f = 0; f < 8; f++) {
                const int w = (f * 8 + g) * 36 + kk * 8 + t;
                unsigned bfr[2] = { Vw[w], Vw[w + 4] };
                mma_h(cO[f], a, bfr);
            }
        }
    }

    // epilogue: normalize, fp16-round, write ctx [s][h*d]
    const float inv0 = 1.0f / l0_;
    const float inv1 = 1.0f / l1_;
    const int q_a = q0 + qrow, q_b = q_a + 8;
    #pragma unroll
    for (int f = 0; f < 8; f++) {
        const int col = h * D_ + f * 8 + t * 2;
        *(unsigned*)(g_ctxh + ((size_t)b * S_ + q_a) * E_ + col) =
            pack2h(cO[f][0] * inv0, cO[f][1] * inv0);
        *(unsigned*)(g_ctxh + ((size_t)b * S_ + q_b) * E_ + col) =
            pack2h(cO[f][2] * inv1, cO[f][3] * inv1);
    }
}

// ---------------------------------------------------------------------------
extern "C" void kernel_launch(void* const* d_in, const int* in_sizes, int n_in,
                              void* d_out, int out_size)
{
    const float* x  = (const float*)d_in[0];
    const float* Wq = (const float*)d_in[1];
    const float* Wk = (const float*)d_in[2];
    const float* Wv = (const float*)d_in[3];
    const float* bq = (const float*)d_in[4];
    const float* bk = (const float*)d_in[5];
    const float* bv = (const float*)d_in[6];
    const float* Wo = (const float*)d_in[7];
    const float* bo = (const float*)d_in[8];
    float* out = (float*)d_out;

    cudaFuncSetAttribute(qkv_kernel,   cudaFuncAttributeMaxDynamicSharedMemorySize, GEMM_SMEM);
    cudaFuncSetAttribute(flash_kernel, cudaFuncAttributeMaxDynamicSharedMemorySize, FLASH_SMEM);
    cudaFuncSetAttribute(oproj_kernel, cudaFuncAttributeMaxDynamicSharedMemorySize, GEMM_SMEM);

    prep_kernel<<<2368, 256>>>(x, Wq, Wk, Wv, Wo);
    qkv_kernel<<<dim3(BS_ / 128, 24), 256, GEMM_SMEM>>>(bq, bk, bv);
    flash_kernel<<<dim3(S_ / 128, H_, B_), 256, FLASH_SMEM>>>();
    oproj_kernel<<<dim3(BS_ / 128, E_ / 128), 256, GEMM_SMEM>>>(bo, out);
}

// round 8
// speedup vs baseline: 2.0412x; 1.1203x over previous
#include <cuda_runtime.h>
#include <cuda_fp16.h>
#include <cstdint>

#define B_ 4
#define S_ 2048
#define E_ 1024
#define H_ 16
#define D_ 64
#define BS_ (B_*S_)
#define BHSD (B_*H_*S_*D_)
#define LOG2E 1.4426950408889634f

// Scratch (device globals — no allocations allowed). All fp16.
__device__ __align__(16) __half g_qh[(size_t)BHSD];        // [b,h][s][d], pre-scaled
__device__ __align__(16) __half g_kh[(size_t)BHSD];        // [b,h][s][d]
__device__ __align__(16) __half g_vh[(size_t)BHSD];        // [b,h][d][s]  (transposed)
__device__ __align__(16) __half g_ctxh[(size_t)BS_*E_];    // [s][h*d]
__device__ __align__(16) __half g_xh[(size_t)BS_*E_];      // [s][e]
__device__ __align__(16) __half g_Wqh[H_*E_*D_];           // [h][d][e]
__device__ __align__(16) __half g_Wkh[H_*E_*D_];           // [h][d][e]
__device__ __align__(16) __half g_Wvh[H_*E_*D_];           // [h][d][e]
__device__ __align__(16) __half g_Woh[H_*D_*E_];           // [n][k]

// ---------------------------------------------------------------------------
__device__ __forceinline__ unsigned pack2h(float a, float b) {
    __half2 h = __floats2half2_rn(a, b);
    return *(unsigned*)&h;
}
__device__ __forceinline__ void mma_h(float* c, const unsigned* a, const unsigned* b) {
    asm volatile(
        "mma.sync.aligned.m16n8k16.row.col.f32.f16.f16.f32 "
        "{%0,%1,%2,%3}, {%4,%5,%6,%7}, {%8,%9}, {%0,%1,%2,%3};\n"
        : "+f"(c[0]), "+f"(c[1]), "+f"(c[2]), "+f"(c[3])
        : "r"(a[0]), "r"(a[1]), "r"(a[2]), "r"(a[3]), "r"(b[0]), "r"(b[1]));
}
__device__ __forceinline__ void ldsm4(unsigned* r, uint32_t a) {
    asm volatile("ldmatrix.sync.aligned.m8n8.x4.shared.b16 {%0,%1,%2,%3}, [%4];"
        : "=r"(r[0]), "=r"(r[1]), "=r"(r[2]), "=r"(r[3]) : "r"(a));
}
__device__ __forceinline__ void cp16(uint32_t d, const __half* s) {
    asm volatile("cp.async.cg.shared.global [%0], [%1], 16;\n" :: "r"(d), "l"(s));
}
__device__ __forceinline__ void cp_commit() { asm volatile("cp.async.commit_group;\n"); }
__device__ __forceinline__ void cp_wait0()  { asm volatile("cp.async.wait_group 0;\n" ::: "memory"); }

// ---------------------------------------------------------------------------
// prep: fp16-convert x; transpose+convert Wq/Wk/Wv -> [h][d][e]; Wo -> [n][k]
// ---------------------------------------------------------------------------
#define N4_X  (BS_*E_/4)
#define N4_W  (H_*E_*D_/4)
#define N4_TOT (N4_X + 4*N4_W)

__global__ void prep_kernel(const float* __restrict__ x,
                            const float* __restrict__ Wq, const float* __restrict__ Wk,
                            const float* __restrict__ Wv, const float* __restrict__ Wo)
{
    int i = blockIdx.x * blockDim.x + threadIdx.x;
    int stride = gridDim.x * blockDim.x;
    for (; i < N4_TOT; i += stride) {
        if (i < N4_X) {
            float4 v = ((const float4*)x)[i];
            ((uint2*)g_xh)[i] = make_uint2(pack2h(v.x, v.y), pack2h(v.z, v.w));
        } else if (i < N4_X + 3 * N4_W) {
            int tt = i - N4_X;
            int wsel = tt / N4_W, o4 = tt % N4_W;
            const float* W = (wsel == 0) ? Wq : (wsel == 1) ? Wk : Wv;
            __half* dst = (wsel == 0) ? g_Wqh : (wsel == 1) ? g_Wkh : g_Wvh;
            int o = o4 * 4;
            int e = o & (E_ - 1);
            int rest = o >> 10;
            int d = rest & (D_ - 1);
            int hh = rest >> 6;
            const float* src = W + (size_t)hh * E_ * D_ + d;
            float v0 = src[(size_t)(e + 0) * D_];
            float v1 = src[(size_t)(e + 1) * D_];
            float v2 = src[(size_t)(e + 2) * D_];
            float v3 = src[(size_t)(e + 3) * D_];
            ((uint2*)dst)[o4] = make_uint2(pack2h(v0, v1), pack2h(v2, v3));
        } else {
            int o4 = i - N4_X - 3 * N4_W;
            int o = o4 * 4;
            int k = o & 1023;
            int n = o >> 10;
            float v0 = Wo[(size_t)(k + 0) * E_ + n];
            float v1 = Wo[(size_t)(k + 1) * E_ + n];
            float v2 = Wo[(size_t)(k + 2) * E_ + n];
            float v3 = Wo[(size_t)(k + 3) * E_ + n];
            ((uint2*)g_Woh)[o4] = make_uint2(pack2h(v0, v1), pack2h(v2, v3));
        }
    }
}

// ---------------------------------------------------------------------------
// GEMM skeleton (fp16 m16n8k16 + ldmatrix): CTA tile 128x128, K-tile 32,
// 3-stage ring, 256 thr / 8 warps (wm 0..3 x wn 0..1, warp tile 32x64).
// smem rows padded to 40 halves (80B): conflict-free LDSM.
// ---------------------------------------------------------------------------
#define GEMM_SMEM 61440
#define A_STB(s) ((uint32_t)(s) * 10240u)
#define B_STB(s) (30720u + (uint32_t)(s) * 10240u)

__device__ __forceinline__ void gemm_tile(float c[2][8][4], uint32_t aB, uint32_t bB,
                                          int wm, int wn, int lane)
{
    const int i8  = lane & 7;
    const int sel = lane >> 3;          // matrix index within x4
    const int arow_off = (sel & 1) * 8 + i8;
    const int akof     = (sel >> 1) * 8;
    const int bfsel    = sel >> 1;
    const int bkof     = (sel & 1) * 8;
    #pragma unroll
    for (int ks = 0; ks < 2; ks++) {
        unsigned a[2][4];
        #pragma unroll
        for (int mi = 0; mi < 2; mi++) {
            const int row = wm * 32 + mi * 16 + arow_off;
            ldsm4(a[mi], aB + (uint32_t)(row * 80 + (ks * 16 + akof) * 2));
        }
        #pragma unroll
        for (int j = 0; j < 4; j++) {
            unsigned bq[4];
            const int row = wn * 64 + (2 * j + bfsel) * 8 + i8;
            ldsm4(bq, bB + (uint32_t)(row * 80 + (ks * 16 + bkof) * 2));
            mma_h(c[0][2 * j],     a[0], bq);
            mma_h(c[1][2 * j],     a[1], bq);
            mma_h(c[0][2 * j + 1], a[0], bq + 2);
            mma_h(c[1][2 * j + 1], a[1], bq + 2);
        }
    }
}

// ---------------------------------------------------------------------------
// Kernel 1: fused QKV projection. grid (64, 24), 256 threads, 2 CTA/SM.
// ---------------------------------------------------------------------------
__global__ __launch_bounds__(256, 2) void qkv_kernel(
    const float* __restrict__ bq, const float* __restrict__ bk, const float* __restrict__ bv)
{
    extern __shared__ char smc[];
    const int tid  = threadIdx.x;
    const int m0   = blockIdx.x * 128;
    const int p0   = blockIdx.y * 2;
    const int lane = tid & 31, wid = tid >> 5;
    const int wm   = wid >> 1, wn = wid & 1;
    const int g    = lane >> 2, t = lane & 3;
    const uint32_t smb = (uint32_t)__cvta_generic_to_shared(smc);

    const __half* aS[2]; uint32_t aO[2];
    const __half* bS[2]; uint32_t bO[2];
    #pragma unroll
    for (int i = 0; i < 2; i++) {
        int c = tid + i * 256;
        int row = c >> 2, cpos = c & 3;
        aS[i] = g_xh + (size_t)(m0 + row) * E_ + cpos * 8;
        aO[i] = (uint32_t)(row * 80 + cpos * 16);
        int p = p0 + (row >> 6), op = p >> 4, hh = p & 15, d = row & 63;
        const __half* base = (op == 0) ? g_Wqh : (op == 1) ? g_Wkh : g_Wvh;
        bS[i] = base + ((size_t)hh * D_ + d) * E_ + cpos * 8;
        bO[i] = aO[i];
    }

    #pragma unroll
    for (int ss = 0; ss < 2; ss++) {
        #pragma unroll
        for (int i = 0; i < 2; i++) {
            cp16(smb + A_STB(ss) + aO[i], aS[i] + ss * 32);
            cp16(smb + B_STB(ss) + bO[i], bS[i] + ss * 32);
        }
        cp_commit();
    }

    float c[2][8][4];
    #pragma unroll
    for (int mi = 0; mi < 2; mi++)
        #pragma unroll
        for (int f = 0; f < 8; f++)
            #pragma unroll
            for (int r = 0; r < 4; r++) c[mi][f][r] = 0.f;

    for (int kt = 0; kt < 32; kt++) {
        if (kt < 31) asm volatile("cp.async.wait_group 1;" ::: "memory");
        else         cp_wait0();
        __syncthreads();
        if (kt + 2 < 32) {
            const int s = (kt + 2) % 3;
            #pragma unroll
            for (int i = 0; i < 2; i++) {
                cp16(smb + A_STB(s) + aO[i], aS[i] + (size_t)(kt + 2) * 32);
                cp16(smb + B_STB(s) + bO[i], bS[i] + (size_t)(kt + 2) * 32);
            }
            cp_commit();
        }
        const int st = kt % 3;
        gemm_tile(c, smb + A_STB(st), smb + B_STB(st), wm, wn, lane);
    }

    // epilogue: bias, scale Q, fp16-round, store
    const int p  = p0 + wn;
    const int op = p >> 4, hh = p & 15;
    const float* bb = ((op == 0) ? bq : (op == 1) ? bk : bv) + hh * D_;

    #pragma unroll
    for (int mi = 0; mi < 2; mi++) {
        #pragma unroll
        for (int rr = 0; rr < 2; rr++) {
            const int gr = m0 + wm * 32 + mi * 16 + g + rr * 8;
            const int bbi = gr >> 11, ssi = gr & 2047;
            #pragma unroll
            for (int f = 0; f < 8; f++) {
                const int col = f * 8 + t * 2;
                float v0 = c[mi][f][rr * 2 + 0] + bb[col];
                float v1 = c[mi][f][rr * 2 + 1] + bb[col + 1];
                if (op == 0) {
                    v0 *= 0.125f * LOG2E; v1 *= 0.125f * LOG2E;
                    *(unsigned*)(g_qh + (((size_t)bbi * H_ + hh) * S_ + ssi) * D_ + col) = pack2h(v0, v1);
                } else if (op == 1) {
                    *(unsigned*)(g_kh + (((size_t)bbi * H_ + hh) * S_ + ssi) * D_ + col) = pack2h(v0, v1);
                } else {
                    __half* vb = g_vh + ((size_t)bbi * H_ + hh) * D_ * S_ + ssi;
                    vb[(size_t)col * S_]       = __float2half_rn(v0);
                    vb[(size_t)(col + 1) * S_] = __float2half_rn(v1);
                }
            }
        }
    }
}

// ---------------------------------------------------------------------------
// Kernel 3: output projection. grid (64, 8), 256 threads, 2 CTA/SM.
// ---------------------------------------------------------------------------
__global__ __launch_bounds__(256, 2) void oproj_kernel(
    const float* __restrict__ bo, float* __restrict__ out)
{
    extern __shared__ char smc[];
    const int tid  = threadIdx.x;
    const int m0   = blockIdx.x * 128;
    const int n0   = blockIdx.y * 128;
    const int lane = tid & 31, wid = tid >> 5;
    const int wm   = wid >> 1, wn = wid & 1;
    const int g    = lane >> 2, t = lane & 3;
    const uint32_t smb = (uint32_t)__cvta_generic_to_shared(smc);

    const __half* aS[2]; uint32_t aO[2];
    const __half* bS[2];
    #pragma unroll
    for (int i = 0; i < 2; i++) {
        int c = tid + i * 256;
        int row = c >> 2, cpos = c & 3;
        aS[i] = g_ctxh + (size_t)(m0 + row) * E_ + cpos * 8;
        aO[i] = (uint32_t)(row * 80 + cpos * 16);
        bS[i] = g_Woh + (size_t)(n0 + row) * E_ + cpos * 8;
    }

    #pragma unroll
    for (int ss = 0; ss < 2; ss++) {
        #pragma unroll
        for (int i = 0; i < 2; i++) {
            cp16(smb + A_STB(ss) + aO[i], aS[i] + ss * 32);
            cp16(smb + B_STB(ss) + aO[i], bS[i] + ss * 32);
        }
        cp_commit();
    }

    float c[2][8][4];
    #pragma unroll
    for (int mi = 0; mi < 2; mi++)
        #pragma unroll
        for (int f = 0; f < 8; f++)
            #pragma unroll
            for (int r = 0; r < 4; r++) c[mi][f][r] = 0.f;

    for (int kt = 0; kt < 32; kt++) {
        if (kt < 31) asm volatile("cp.async.wait_group 1;" ::: "memory");
        else         cp_wait0();
        __syncthreads();
        if (kt + 2 < 32) {
            const int s = (kt + 2) % 3;
            #pragma unroll
            for (int i = 0; i < 2; i++) {
                cp16(smb + A_STB(s) + aO[i], aS[i] + (size_t)(kt + 2) * 32);
                cp16(smb + B_STB(s) + aO[i], bS[i] + (size_t)(kt + 2) * 32);
            }
            cp_commit();
        }
        const int st = kt % 3;
        gemm_tile(c, smb + A_STB(st), smb + B_STB(st), wm, wn, lane);
    }

    #pragma unroll
    for (int mi = 0; mi < 2; mi++) {
        const int r0 = m0 + wm * 32 + mi * 16 + g;
        #pragma unroll
        for (int f = 0; f < 8; f++) {
            const int col = n0 + wn * 64 + f * 8 + t * 2;
            const float b0v = bo[col], b1v = bo[col + 1];
            float2 v0; v0.x = c[mi][f][0] + b0v; v0.y = c[mi][f][1] + b1v;
            *(float2*)(out + (size_t)r0 * E_ + col) = v0;
            float2 v1; v1.x = c[mi][f][2] + b0v; v1.y = c[mi][f][3] + b1v;
            *(float2*)(out + (size_t)(r0 + 8) * E_ + col) = v1;
        }
    }
}

// ---------------------------------------------------------------------------
// Kernel 2: causal flash attention, fp16 + ldmatrix + register-P (FA2 style).
// Block = 128 queries of one (b,h), Bkv=64, 256 thr / 8 warps, 2 CTA/SM.
// smem rows 72 halves (144B stride): Q[128]@0 | K 2x[64]@18432 | Vt 2x[64]@36864.
// ---------------------------------------------------------------------------
#define FLASH_SMEM 55296
#define FK_STB(s) (18432u + (uint32_t)(s) * 9216u)
#define FV_STB(s) (36864u + (uint32_t)(s) * 9216u)

__global__ __launch_bounds__(256, 2) void flash_kernel()
{
    extern __shared__ char smc[];
    const uint32_t smb = (uint32_t)__cvta_generic_to_shared(smc);

    const int iq = (int)(gridDim.x - 1 - blockIdx.x);   // heavy-first
    const int h = blockIdx.y, b = blockIdx.z;
    const int q0 = iq * 128;
    const size_t head = ((size_t)b * H_ + h) * S_ * D_;
    const __half* Qg = g_qh + head;
    const __half* Kg = g_kh + head;
    const __half* Vg = g_vh + head;

    const int tid  = threadIdx.x;
    const int lane = tid & 31, wid = tid >> 5;
    const int g    = lane >> 2, t = lane & 3;
    const int i8   = lane & 7, sel = lane >> 3;
    const int bfsel = sel >> 1;          // ldmatrix B: n-pair select
    const int bkof  = (sel & 1) * 8;     // ldmatrix B: k-half select
    const int qrow  = wid * 16 + g;

    const __half* kS[2]; const __half* vS[2]; uint32_t kO[2];
    #pragma unroll
    for (int i = 0; i < 2; i++) {
        int c = tid + i * 256;
        int row = c >> 3, cpos = c & 7;
        kS[i] = Kg + (size_t)row * D_ + cpos * 8;
        vS[i] = Vg + (size_t)row * S_ + cpos * 8;
        kO[i] = (uint32_t)(row * 144 + cpos * 16);
    }

    // prologue: Q + K/V tile 0
    #pragma unroll
    for (int i = 0; i < 4; i++) {
        int c = tid + i * 256;
        int row = c >> 3, cpos = c & 7;
        cp16(smb + (uint32_t)(row * 144 + cpos * 16), Qg + (size_t)(q0 + row) * D_ + cpos * 8);
    }
    #pragma unroll
    for (int i = 0; i < 2; i++) {
        cp16(smb + FK_STB(0) + kO[i], kS[i]);
        cp16(smb + FV_STB(0) + kO[i], vS[i]);
    }
    cp_commit();
    cp_wait0();
    __syncthreads();

    // Q fragments via ldmatrix (warp-private rows)
    unsigned aQ[4][4];
    {
        const int row = wid * 16 + (sel & 1) * 8 + i8;
        const int kof = (sel >> 1) * 8;
        #pragma unroll
        for (int kk = 0; kk < 4; kk++)
            ldsm4(aQ[kk], smb + (uint32_t)(row * 144 + (kk * 16 + kof) * 2));
    }

    float cO[8][4];
    #pragma unroll
    for (int f = 0; f < 8; f++)
        #pragma unroll
        for (int r = 0; r < 4; r++) cO[f][r] = 0.f;
    float m0_ = -1e30f, m1_ = -1e30f, l0_ = 0.f, l1_ = 0.f;

    const int jtmax = 2 * iq + 1;
    for (int jt = 0; jt <= jtmax; jt++) {
        if (jt > 0) {
            cp_wait0();
            __syncthreads();
        }
        if (jt < jtmax) {
            const uint32_t st = (uint32_t)((jt + 1) & 1);
            #pragma unroll
            for (int i = 0; i < 2; i++) {
                cp16(smb + FK_STB(st) + kO[i], kS[i] + (size_t)(jt + 1) * 4096);
                cp16(smb + FV_STB(st) + kO[i], vS[i] + (size_t)(jt + 1) * 64);
            }
            cp_commit();
        }
        const uint32_t kBase = smb + FK_STB(jt & 1);
        const uint32_t vBase = smb + FV_STB(jt & 1);
        const int k0 = jt * 64;

        // S = Q K^T  (B fragments via ldmatrix; rows = keys, k = d)
        float cS[8][4];
        #pragma unroll
        for (int f = 0; f < 8; f++)
            #pragma unroll
            for (int r = 0; r < 4; r++) cS[f][r] = 0.f;
        #pragma unroll
        for (int kk = 0; kk < 4; kk++) {
            #pragma unroll
            for (int j = 0; j < 4; j++) {
                unsigned bq[4];
                const int row = (2 * j + bfsel) * 8 + i8;
                ldsm4(bq, kBase + (uint32_t)(row * 144 + (kk * 16 + bkof) * 2));
                mma_h(cS[2 * j],     aQ[kk], bq);
                mma_h(cS[2 * j + 1], aQ[kk], bq + 2);
            }
        }

        // causal mask (diagonal-crossing tiles only)
        if (jt >= 2 * iq) {
            const int r0 = q0 + qrow, r1 = r0 + 8;
            #pragma unroll
            for (int f = 0; f < 8; f++) {
                const int col = k0 + f * 8 + t * 2;
                if (col     > r0) cS[f][0] = -1e30f;
                if (col + 1 > r0) cS[f][1] = -1e30f;
                if (col     > r1) cS[f][2] = -1e30f;
                if (col + 1 > r1) cS[f][3] = -1e30f;
            }
        }

        // online softmax (exp2 domain; Q pre-scaled by 0.125*log2e)
        float rm0 = -1e30f, rm1 = -1e30f;
        #pragma unroll
        for (int f = 0; f < 8; f++) {
            rm0 = fmaxf(rm0, fmaxf(cS[f][0], cS[f][1]));
            rm1 = fmaxf(rm1, fmaxf(cS[f][2], cS[f][3]));
        }
        rm0 = fmaxf(rm0, __shfl_xor_sync(0xffffffffu, rm0, 1));
        rm0 = fmaxf(rm0, __shfl_xor_sync(0xffffffffu, rm0, 2));
        rm1 = fmaxf(rm1, __shfl_xor_sync(0xffffffffu, rm1, 1));
        rm1 = fmaxf(rm1, __shfl_xor_sync(0xffffffffu, rm1, 2));

        const float nm0 = fmaxf(m0_, rm0);
        const float nm1 = fmaxf(m1_, rm1);
        const float corr0 = exp2f(m0_ - nm0);
        const float corr1 = exp2f(m1_ - nm1);
        m0_ = nm0; m1_ = nm1;

        float rs0 = 0.f, rs1 = 0.f;
        #pragma unroll
        for (int f = 0; f < 8; f++) {
            cS[f][0] = exp2f(cS[f][0] - nm0);
            cS[f][1] = exp2f(cS[f][1] - nm0);
            cS[f][2] = exp2f(cS[f][2] - nm1);
            cS[f][3] = exp2f(cS[f][3] - nm1);
            rs0 += cS[f][0] + cS[f][1];
            rs1 += cS[f][2] + cS[f][3];
        }
        rs0 += __shfl_xor_sync(0xffffffffu, rs0, 1);
        rs0 += __shfl_xor_sync(0xffffffffu, rs0, 2);
        rs1 += __shfl_xor_sync(0xffffffffu, rs1, 1);
        rs1 += __shfl_xor_sync(0xffffffffu, rs1, 2);
        l0_ = l0_ * corr0 + rs0;
        l1_ = l1_ * corr1 + rs1;
        #pragma unroll
        for (int f = 0; f < 8; f++) {
            cO[f][0] *= corr0; cO[f][1] *= corr0;
            cO[f][2] *= corr1; cO[f][3] *= corr1;
        }

        // O += P V : P packed from accumulators (no smem roundtrip);
        // B = V^T (rows = d, k = keys) via ldmatrix
        #pragma unroll
        for (int kk = 0; kk < 4; kk++) {
            unsigned aP[4];
            aP[0] = pack2h(cS[2 * kk][0],     cS[2 * kk][1]);
            aP[1] = pack2h(cS[2 * kk][2],     cS[2 * kk][3]);
            aP[2] = pack2h(cS[2 * kk + 1][0], cS[2 * kk + 1][1]);
            aP[3] = pack2h(cS[2 * kk + 1][2], cS[2 * kk + 1][3]);
            #pragma unroll
            for (int j = 0; j < 4; j++) {
                unsigned bq[4];
                const int row = (2 * j + bfsel) * 8 + i8;
                ldsm4(bq, vBase + (uint32_t)(row * 144 + (kk * 16 + bkof) * 2));
                mma_h(cO[2 * j],     aP, bq);
                mma_h(cO[2 * j + 1], aP, bq + 2);
            }
        }
    }

    // epilogue: normalize, fp16-round, write ctx [s][h*d]
    const float inv0 = 1.0f / l0_;
    const float inv1 = 1.0f / l1_;
    const int q_a = q0 + qrow, q_b = q_a + 8;
    #pragma unroll
    for (int f = 0; f < 8; f++) {
        const int col = h * D_ + f * 8 + t * 2;
        *(unsigned*)(g_ctxh + ((size_t)b * S_ + q_a) * E_ + col) =
            pack2h(cO[f][0] * inv0, cO[f][1] * inv0);
        *(unsigned*)(g_ctxh + ((size_t)b * S_ + q_b) * E_ + col) =
            pack2h(cO[f][2] * inv1, cO[f][3] * inv1);
    }
}

// ---------------------------------------------------------------------------
extern "C" void kernel_launch(void* const* d_in, const int* in_sizes, int n_in,
                              void* d_out, int out_size)
{
    const float* x  = (const float*)d_in[0];
    const float* Wq = (const float*)d_in[1];
    const float* Wk = (const float*)d_in[2];
    const float* Wv = (const float*)d_in[3];
    const float* bq = (const float*)d_in[4];
    const float* bk = (const float*)d_in[5];
    const float* bv = (const float*)d_in[6];
    const float* Wo = (const float*)d_in[7];
    const float* bo = (const float*)d_in[8];
    float* out = (float*)d_out;

    cudaFuncSetAttribute(qkv_kernel,   cudaFuncAttributeMaxDynamicSharedMemorySize, GEMM_SMEM);
    cudaFuncSetAttribute(flash_kernel, cudaFuncAttributeMaxDynamicSharedMemorySize, FLASH_SMEM);
    cudaFuncSetAttribute(oproj_kernel, cudaFuncAttributeMaxDynamicSharedMemorySize, GEMM_SMEM);

    prep_kernel<<<2368, 256>>>(x, Wq, Wk, Wv, Wo);
    qkv_kernel<<<dim3(BS_ / 128, 24), 256, GEMM_SMEM>>>(bq, bk, bv);
    flash_kernel<<<dim3(S_ / 128, H_, B_), 256, FLASH_SMEM>>>();
    oproj_kernel<<<dim3(BS_ / 128, E_ / 128), 256, GEMM_SMEM>>>(bo, out);
}

// round 9
// speedup vs baseline: 2.2495x; 1.1020x over previous
#include <cuda_runtime.h>
#include <cuda_fp16.h>
#include <cstdint>

#define B_ 4
#define S_ 2048
#define E_ 1024
#define H_ 16
#define D_ 64
#define BS_ (B_*S_)
#define BHSD (B_*H_*S_*D_)
#define LOG2E 1.4426950408889634f

// Scratch (device globals — no allocations allowed). All fp16.
__device__ __align__(16) __half g_qh[(size_t)BHSD];        // [b,h][s][d], pre-scaled
__device__ __align__(16) __half g_kh[(size_t)BHSD];        // [b,h][s][d]
__device__ __align__(16) __half g_vh[(size_t)BHSD];        // [b,h][s][d] (same as K now)
__device__ __align__(16) __half g_ctxh[(size_t)BS_*E_];    // [s][h*d]
__device__ __align__(16) __half g_xh[(size_t)BS_*E_];      // [s][e]
__device__ __align__(16) __half g_Wqh[H_*E_*D_];           // [h][d][e]
__device__ __align__(16) __half g_Wkh[H_*E_*D_];           // [h][d][e]
__device__ __align__(16) __half g_Wvh[H_*E_*D_];           // [h][d][e]
__device__ __align__(16) __half g_Woh[H_*D_*E_];           // [n][k]

// ---------------------------------------------------------------------------
__device__ __forceinline__ unsigned pack2h(float a, float b) {
    __half2 h = __floats2half2_rn(a, b);
    return *(unsigned*)&h;
}
__device__ __forceinline__ void mma_h(float* c, const unsigned* a, const unsigned* b) {
    asm volatile(
        "mma.sync.aligned.m16n8k16.row.col.f32.f16.f16.f32 "
        "{%0,%1,%2,%3}, {%4,%5,%6,%7}, {%8,%9}, {%0,%1,%2,%3};\n"
        : "+f"(c[0]), "+f"(c[1]), "+f"(c[2]), "+f"(c[3])
        : "r"(a[0]), "r"(a[1]), "r"(a[2]), "r"(a[3]), "r"(b[0]), "r"(b[1]));
}
__device__ __forceinline__ void ldsm4(unsigned* r, uint32_t a) {
    asm volatile("ldmatrix.sync.aligned.m8n8.x4.shared.b16 {%0,%1,%2,%3}, [%4];"
        : "=r"(r[0]), "=r"(r[1]), "=r"(r[2]), "=r"(r[3]) : "r"(a));
}
__device__ __forceinline__ void ldsm4t(unsigned* r, uint32_t a) {
    asm volatile("ldmatrix.sync.aligned.m8n8.x4.trans.shared.b16 {%0,%1,%2,%3}, [%4];"
        : "=r"(r[0]), "=r"(r[1]), "=r"(r[2]), "=r"(r[3]) : "r"(a));
}
__device__ __forceinline__ void cp16(uint32_t d, const __half* s) {
    asm volatile("cp.async.cg.shared.global [%0], [%1], 16;\n" :: "r"(d), "l"(s));
}
__device__ __forceinline__ void cp_commit() { asm volatile("cp.async.commit_group;\n"); }
__device__ __forceinline__ void cp_wait0()  { asm volatile("cp.async.wait_group 0;\n" ::: "memory"); }

// ---------------------------------------------------------------------------
// prep: fp16-convert x; transpose+convert Wq/Wk/Wv -> [h][d][e]; Wo -> [n][k]
// ---------------------------------------------------------------------------
#define N4_X  (BS_*E_/4)
#define N4_W  (H_*E_*D_/4)
#define N4_TOT (N4_X + 4*N4_W)

__global__ void prep_kernel(const float* __restrict__ x,
                            const float* __restrict__ Wq, const float* __restrict__ Wk,
                            const float* __restrict__ Wv, const float* __restrict__ Wo)
{
    int i = blockIdx.x * blockDim.x + threadIdx.x;
    int stride = gridDim.x * blockDim.x;
    for (; i < N4_TOT; i += stride) {
        if (i < N4_X) {
            float4 v = ((const float4*)x)[i];
            ((uint2*)g_xh)[i] = make_uint2(pack2h(v.x, v.y), pack2h(v.z, v.w));
        } else if (i < N4_X + 3 * N4_W) {
            int tt = i - N4_X;
            int wsel = tt / N4_W, o4 = tt % N4_W;
            const float* W = (wsel == 0) ? Wq : (wsel == 1) ? Wk : Wv;
            __half* dst = (wsel == 0) ? g_Wqh : (wsel == 1) ? g_Wkh : g_Wvh;
            int o = o4 * 4;
            int e = o & (E_ - 1);
            int rest = o >> 10;
            int d = rest & (D_ - 1);
            int hh = rest >> 6;
            const float* src = W + (size_t)hh * E_ * D_ + d;
            float v0 = src[(size_t)(e + 0) * D_];
            float v1 = src[(size_t)(e + 1) * D_];
            float v2 = src[(size_t)(e + 2) * D_];
            float v3 = src[(size_t)(e + 3) * D_];
            ((uint2*)dst)[o4] = make_uint2(pack2h(v0, v1), pack2h(v2, v3));
        } else {
            int o4 = i - N4_X - 3 * N4_W;
            int o = o4 * 4;
            int k = o & 1023;
            int n = o >> 10;
            float v0 = Wo[(size_t)(k + 0) * E_ + n];
            float v1 = Wo[(size_t)(k + 1) * E_ + n];
            float v2 = Wo[(size_t)(k + 2) * E_ + n];
            float v3 = Wo[(size_t)(k + 3) * E_ + n];
            ((uint2*)g_Woh)[o4] = make_uint2(pack2h(v0, v1), pack2h(v2, v3));
        }
    }
}

// ---------------------------------------------------------------------------
// GEMM skeleton: CTA tile 128x128, K-tile 64, 2-stage ring, 256 thr / 8 warps
// (wm 0..3 x wn 0..1, warp tile 32x64). Row stride 72 halves (144B):
// conflict-free LDSM. Stage = 128*144 = 18432 B per operand.
// ---------------------------------------------------------------------------
#define GEMM_SMEM 73728
#define A_STB(s) ((uint32_t)(s) * 18432u)
#define B_STB(s) (36864u + (uint32_t)(s) * 18432u)

__device__ __forceinline__ void gemm_tile64(float c[2][8][4], uint32_t aB, uint32_t bB,
                                            int wm, int wn, int lane)
{
    const int i8  = lane & 7;
    const int sel = lane >> 3;
    const int arow_off = (sel & 1) * 8 + i8;
    const int akof     = (sel >> 1) * 8;
    const int bfsel    = sel >> 1;
    const int bkof     = (sel & 1) * 8;
    #pragma unroll
    for (int ks = 0; ks < 4; ks++) {
        unsigned a[2][4];
        #pragma unroll
        for (int mi = 0; mi < 2; mi++) {
            const int row = wm * 32 + mi * 16 + arow_off;
            ldsm4(a[mi], aB + (uint32_t)(row * 144 + (ks * 16 + akof) * 2));
        }
        #pragma unroll
        for (int j = 0; j < 4; j++) {
            unsigned bq[4];
            const int row = wn * 64 + (2 * j + bfsel) * 8 + i8;
            ldsm4(bq, bB + (uint32_t)(row * 144 + (ks * 16 + bkof) * 2));
            mma_h(c[0][2 * j],     a[0], bq);
            mma_h(c[1][2 * j],     a[1], bq);
            mma_h(c[0][2 * j + 1], a[0], bq + 2);
            mma_h(c[1][2 * j + 1], a[1], bq + 2);
        }
    }
}

// ---------------------------------------------------------------------------
// Kernel 1: fused QKV projection. grid (64, 24), 256 threads, 2 CTA/SM.
// ---------------------------------------------------------------------------
__global__ __launch_bounds__(256, 2) void qkv_kernel(
    const float* __restrict__ bq, const float* __restrict__ bk, const float* __restrict__ bv)
{
    extern __shared__ char smc[];
    const int tid  = threadIdx.x;
    const int m0   = blockIdx.x * 128;
    const int p0   = blockIdx.y * 2;
    const int lane = tid & 31, wid = tid >> 5;
    const int wm   = wid >> 1, wn = wid & 1;
    const int g    = lane >> 2, t = lane & 3;
    const uint32_t smb = (uint32_t)__cvta_generic_to_shared(smc);

    // per-tile: A 1024 chunks of 16B, B 1024 chunks; 4 each per thread
    const __half* aS[4]; uint32_t aO[4];
    const __half* bS[4];
    #pragma unroll
    for (int i = 0; i < 4; i++) {
        int c = tid + i * 256;
        int row = c >> 3, cpos = c & 7;
        aS[i] = g_xh + (size_t)(m0 + row) * E_ + cpos * 8;
        aO[i] = (uint32_t)(row * 144 + cpos * 16);
        int p = p0 + (row >> 6), op = p >> 4, hh = p & 15, d = row & 63;
        const __half* base = (op == 0) ? g_Wqh : (op == 1) ? g_Wkh : g_Wvh;
        bS[i] = base + ((size_t)hh * D_ + d) * E_ + cpos * 8;
    }

    // prologue: tile 0 -> stage 0
    #pragma unroll
    for (int i = 0; i < 4; i++) {
        cp16(smb + A_STB(0) + aO[i], aS[i]);
        cp16(smb + B_STB(0) + aO[i], bS[i]);
    }
    cp_commit();

    float c[2][8][4];
    #pragma unroll
    for (int mi = 0; mi < 2; mi++)
        #pragma unroll
        for (int f = 0; f < 8; f++)
            #pragma unroll
            for (int r = 0; r < 4; r++) c[mi][f][r] = 0.f;

    for (int kt = 0; kt < 16; kt++) {
        cp_wait0();
        __syncthreads();
        if (kt + 1 < 16) {
            const uint32_t s = (uint32_t)((kt + 1) & 1);
            #pragma unroll
            for (int i = 0; i < 4; i++) {
                cp16(smb + A_STB(s) + aO[i], aS[i] + (size_t)(kt + 1) * 64);
                cp16(smb + B_STB(s) + aO[i], bS[i] + (size_t)(kt + 1) * 64);
            }
            cp_commit();
        }
        gemm_tile64(c, smb + A_STB(kt & 1), smb + B_STB(kt & 1), wm, wn, lane);
    }

    // epilogue: bias, scale Q, fp16-round, coalesced store (V same layout as K)
    const int p  = p0 + wn;
    const int op = p >> 4, hh = p & 15;
    const float* bb = ((op == 0) ? bq : (op == 1) ? bk : bv) + hh * D_;
    __half* outb = (op == 0) ? g_qh : (op == 1) ? g_kh : g_vh;
    const float scl = (op == 0) ? (0.125f * LOG2E) : 1.0f;

    #pragma unroll
    for (int mi = 0; mi < 2; mi++) {
        #pragma unroll
        for (int rr = 0; rr < 2; rr++) {
            const int gr = m0 + wm * 32 + mi * 16 + g + rr * 8;
            const int bbi = gr >> 11, ssi = gr & 2047;
            __half* ob = outb + (((size_t)bbi * H_ + hh) * S_ + ssi) * D_;
            #pragma unroll
            for (int f = 0; f < 8; f++) {
                const int col = f * 8 + t * 2;
                float v0 = (c[mi][f][rr * 2 + 0] + bb[col])     * scl;
                float v1 = (c[mi][f][rr * 2 + 1] + bb[col + 1]) * scl;
                *(unsigned*)(ob + col) = pack2h(v0, v1);
            }
        }
    }
}

// ---------------------------------------------------------------------------
// Kernel 3: output projection. grid (64, 8), 256 threads, 2 CTA/SM.
// ---------------------------------------------------------------------------
__global__ __launch_bounds__(256, 2) void oproj_kernel(
    const float* __restrict__ bo, float* __restrict__ out)
{
    extern __shared__ char smc[];
    const int tid  = threadIdx.x;
    const int m0   = blockIdx.x * 128;
    const int n0   = blockIdx.y * 128;
    const int lane = tid & 31, wid = tid >> 5;
    const int wm   = wid >> 1, wn = wid & 1;
    const int g    = lane >> 2, t = lane & 3;
    const uint32_t smb = (uint32_t)__cvta_generic_to_shared(smc);

    const __half* aS[4]; uint32_t aO[4];
    const __half* bS[4];
    #pragma unroll
    for (int i = 0; i < 4; i++) {
        int c = tid + i * 256;
        int row = c >> 3, cpos = c & 7;
        aS[i] = g_ctxh + (size_t)(m0 + row) * E_ + cpos * 8;
        aO[i] = (uint32_t)(row * 144 + cpos * 16);
        bS[i] = g_Woh + (size_t)(n0 + row) * E_ + cpos * 8;
    }

    #pragma unroll
    for (int i = 0; i < 4; i++) {
        cp16(smb + A_STB(0) + aO[i], aS[i]);
        cp16(smb + B_STB(0) + aO[i], bS[i]);
    }
    cp_commit();

    float c[2][8][4];
    #pragma unroll
    for (int mi = 0; mi < 2; mi++)
        #pragma unroll
        for (int f = 0; f < 8; f++)
            #pragma unroll
            for (int r = 0; r < 4; r++) c[mi][f][r] = 0.f;

    for (int kt = 0; kt < 16; kt++) {
        cp_wait0();
        __syncthreads();
        if (kt + 1 < 16) {
            const uint32_t s = (uint32_t)((kt + 1) & 1);
            #pragma unroll
            for (int i = 0; i < 4; i++) {
                cp16(smb + A_STB(s) + aO[i], aS[i] + (size_t)(kt + 1) * 64);
                cp16(smb + B_STB(s) + aO[i], bS[i] + (size_t)(kt + 1) * 64);
            }
            cp_commit();
        }
        gemm_tile64(c, smb + A_STB(kt & 1), smb + B_STB(kt & 1), wm, wn, lane);
    }

    #pragma unroll
    for (int mi = 0; mi < 2; mi++) {
        const int r0 = m0 + wm * 32 + mi * 16 + g;
        #pragma unroll
        for (int f = 0; f < 8; f++) {
            const int col = n0 + wn * 64 + f * 8 + t * 2;
            const float b0v = bo[col], b1v = bo[col + 1];
            float2 v0; v0.x = c[mi][f][0] + b0v; v0.y = c[mi][f][1] + b1v;
            *(float2*)(out + (size_t)r0 * E_ + col) = v0;
            float2 v1; v1.x = c[mi][f][2] + b0v; v1.y = c[mi][f][3] + b1v;
            *(float2*)(out + (size_t)(r0 + 8) * E_ + col) = v1;
        }
    }
}

// ---------------------------------------------------------------------------
// Kernel 2: causal flash attention, fp16 + ldmatrix (+trans for V) + reg-P.
// Block = 128 queries of one (b,h), Bkv=64, 256 thr / 8 warps, 2 CTA/SM.
// smem rows 72 halves (144B): Q[128]@0 | K 2x[64]@18432 | V 2x[64]@36864.
// ---------------------------------------------------------------------------
#define FLASH_SMEM 55296
#define FK_STB(s) (18432u + (uint32_t)(s) * 9216u)
#define FV_STB(s) (36864u + (uint32_t)(s) * 9216u)

__global__ __launch_bounds__(256, 2) void flash_kernel()
{
    extern __shared__ char smc[];
    const uint32_t smb = (uint32_t)__cvta_generic_to_shared(smc);

    const int iq = (int)(gridDim.x - 1 - blockIdx.x);   // heavy-first
    const int h = blockIdx.y, b = blockIdx.z;
    const int q0 = iq * 128;
    const size_t head = ((size_t)b * H_ + h) * S_ * D_;
    const __half* Qg = g_qh + head;
    const __half* Kg = g_kh + head;
    const __half* Vg = g_vh + head;

    const int tid  = threadIdx.x;
    const int lane = tid & 31, wid = tid >> 5;
    const int g    = lane >> 2, t = lane & 3;
    const int i8   = lane & 7, sel = lane >> 3;
    const int bfsel = sel >> 1;
    const int bkof  = (sel & 1) * 8;
    const int qrow  = wid * 16 + g;

    const __half* kS[2]; uint32_t kO[2];
    #pragma unroll
    for (int i = 0; i < 2; i++) {
        int c = tid + i * 256;
        int row = c >> 3, cpos = c & 7;
        kS[i] = Kg + (size_t)row * D_ + cpos * 8;   // V uses same offsets w/ Vg
        kO[i] = (uint32_t)(row * 144 + cpos * 16);
    }
    const ptrdiff_t v_delta = Vg - Kg;

    // prologue: Q + K/V tile 0
    #pragma unroll
    for (int i = 0; i < 4; i++) {
        int c = tid + i * 256;
        int row = c >> 3, cpos = c & 7;
        cp16(smb + (uint32_t)(row * 144 + cpos * 16), Qg + (size_t)(q0 + row) * D_ + cpos * 8);
    }
    #pragma unroll
    for (int i = 0; i < 2; i++) {
        cp16(smb + FK_STB(0) + kO[i], kS[i]);
        cp16(smb + FV_STB(0) + kO[i], kS[i] + v_delta);
    }
    cp_commit();
    cp_wait0();
    __syncthreads();

    // Q fragments via ldmatrix (warp-private rows)
    unsigned aQ[4][4];
    {
        const int row = wid * 16 + (sel & 1) * 8 + i8;
        const int kof = (sel >> 1) * 8;
        #pragma unroll
        for (int kk = 0; kk < 4; kk++)
            ldsm4(aQ[kk], smb + (uint32_t)(row * 144 + (kk * 16 + kof) * 2));
    }

    float cO[8][4];
    #pragma unroll
    for (int f = 0; f < 8; f++)
        #pragma unroll
        for (int r = 0; r < 4; r++) cO[f][r] = 0.f;
    float m0_ = -1e30f, m1_ = -1e30f, l0_ = 0.f, l1_ = 0.f;

    const int jtmax = 2 * iq + 1;
    for (int jt = 0; jt <= jtmax; jt++) {
        if (jt > 0) {
            cp_wait0();
            __syncthreads();
        }
        if (jt < jtmax) {
            const uint32_t st = (uint32_t)((jt + 1) & 1);
            #pragma unroll
            for (int i = 0; i < 2; i++) {
                cp16(smb + FK_STB(st) + kO[i], kS[i] + (size_t)(jt + 1) * 4096);
                cp16(smb + FV_STB(st) + kO[i], kS[i] + v_delta + (size_t)(jt + 1) * 4096);
            }
            cp_commit();
        }
        const uint32_t kBase = smb + FK_STB(jt & 1);
        const uint32_t vBase = smb + FV_STB(jt & 1);
        const int k0 = jt * 64;

        // S = Q K^T  (K stored [key][d]; B-frag non-trans: rows=keys, k=d)
        float cS[8][4];
        #pragma unroll
        for (int f = 0; f < 8; f++)
            #pragma unroll
            for (int r = 0; r < 4; r++) cS[f][r] = 0.f;
        #pragma unroll
        for (int kk = 0; kk < 4; kk++) {
            #pragma unroll
            for (int j = 0; j < 4; j++) {
                unsigned bq[4];
                const int row = (2 * j + bfsel) * 8 + i8;
                ldsm4(bq, kBase + (uint32_t)(row * 144 + (kk * 16 + bkof) * 2));
                mma_h(cS[2 * j],     aQ[kk], bq);
                mma_h(cS[2 * j + 1], aQ[kk], bq + 2);
            }
        }

        // causal mask (diagonal-crossing tiles only)
        if (jt >= 2 * iq) {
            const int r0 = q0 + qrow, r1 = r0 + 8;
            #pragma unroll
            for (int f = 0; f < 8; f++) {
                const int col = k0 + f * 8 + t * 2;
                if (col     > r0) cS[f][0] = -1e30f;
                if (col + 1 > r0) cS[f][1] = -1e30f;
                if (col     > r1) cS[f][2] = -1e30f;
                if (col + 1 > r1) cS[f][3] = -1e30f;
            }
        }

        // online softmax (exp2 domain; Q pre-scaled by 0.125*log2e)
        float rm0 = -1e30f, rm1 = -1e30f;
        #pragma unroll
        for (int f = 0; f < 8; f++) {
            rm0 = fmaxf(rm0, fmaxf(cS[f][0], cS[f][1]));
            rm1 = fmaxf(rm1, fmaxf(cS[f][2], cS[f][3]));
        }
        rm0 = fmaxf(rm0, __shfl_xor_sync(0xffffffffu, rm0, 1));
        rm0 = fmaxf(rm0, __shfl_xor_sync(0xffffffffu, rm0, 2));
        rm1 = fmaxf(rm1, __shfl_xor_sync(0xffffffffu, rm1, 1));
        rm1 = fmaxf(rm1, __shfl_xor_sync(0xffffffffu, rm1, 2));

        const float nm0 = fmaxf(m0_, rm0);
        const float nm1 = fmaxf(m1_, rm1);
        const float corr0 = exp2f(m0_ - nm0);
        const float corr1 = exp2f(m1_ - nm1);
        m0_ = nm0; m1_ = nm1;

        float rs0 = 0.f, rs1 = 0.f;
        #pragma unroll
        for (int f = 0; f < 8; f++) {
            cS[f][0] = exp2f(cS[f][0] - nm0);
            cS[f][1] = exp2f(cS[f][1] - nm0);
            cS[f][2] = exp2f(cS[f][2] - nm1);
            cS[f][3] = exp2f(cS[f][3] - nm1);
            rs0 += cS[f][0] + cS[f][1];
            rs1 += cS[f][2] + cS[f][3];
        }
        rs0 += __shfl_xor_sync(0xffffffffu, rs0, 1);
        rs0 += __shfl_xor_sync(0xffffffffu, rs0, 2);
        rs1 += __shfl_xor_sync(0xffffffffu, rs1, 1);
        rs1 += __shfl_xor_sync(0xffffffffu, rs1, 2);
        l0_ = l0_ * corr0 + rs0;
        l1_ = l1_ * corr1 + rs1;
        #pragma unroll
        for (int f = 0; f < 8; f++) {
            cO[f][0] *= corr0; cO[f][1] *= corr0;
            cO[f][2] *= corr1; cO[f][3] *= corr1;
        }

        // O += P V : P packed from accumulators; V stored [key][d],
        // B-frag via ldmatrix.trans (rows=keys addressed, transposed to [d][key])
        #pragma unroll
        for (int kk = 0; kk < 4; kk++) {
            unsigned aP[4];
            aP[0] = pack2h(cS[2 * kk][0],     cS[2 * kk][1]);
            aP[1] = pack2h(cS[2 * kk][2],     cS[2 * kk][3]);
            aP[2] = pack2h(cS[2 * kk + 1][0], cS[2 * kk + 1][1]);
            aP[3] = pack2h(cS[2 * kk + 1][2], cS[2 * kk + 1][3]);
            #pragma unroll
            for (int j = 0; j < 4; j++) {
                unsigned bq[4];
                const int row = kk * 16 + (sel & 1) * 8 + i8;          // key rows
                const int colb = (2 * j + (sel >> 1)) * 16;            // d-group bytes
                ldsm4t(bq, vBase + (uint32_t)(row * 144 + colb));
                mma_h(cO[2 * j],     aP, bq);
                mma_h(cO[2 * j + 1], aP, bq + 2);
            }
        }
    }

    // epilogue: normalize, fp16-round, write ctx [s][h*d]
    const float inv0 = 1.0f / l0_;
    const float inv1 = 1.0f / l1_;
    const int q_a = q0 + qrow, q_b = q_a + 8;
    #pragma unroll
    for (int f = 0; f < 8; f++) {
        const int col = h * D_ + f * 8 + t * 2;
        *(unsigned*)(g_ctxh + ((size_t)b * S_ + q_a) * E_ + col) =
            pack2h(cO[f][0] * inv0, cO[f][1] * inv0);
        *(unsigned*)(g_ctxh + ((size_t)b * S_ + q_b) * E_ + col) =
            pack2h(cO[f][2] * inv1, cO[f][3] * inv1);
    }
}

// ---------------------------------------------------------------------------
extern "C" void kernel_launch(void* const* d_in, const int* in_sizes, int n_in,
                              void* d_out, int out_size)
{
    const float* x  = (const float*)d_in[0];
    const float* Wq = (const float*)d_in[1];
    const float* Wk = (const float*)d_in[2];
    const float* Wv = (const float*)d_in[3];
    const float* bq = (const float*)d_in[4];
    const float* bk = (const float*)d_in[5];
    const float* bv = (const float*)d_in[6];
    const float* Wo = (const float*)d_in[7];
    const float* bo = (const float*)d_in[8];
    float* out = (float*)d_out;

    cudaFuncSetAttribute(qkv_kernel,   cudaFuncAttributeMaxDynamicSharedMemorySize, GEMM_SMEM);
    cudaFuncSetAttribute(flash_kernel, cudaFuncAttributeMaxDynamicSharedMemorySize, FLASH_SMEM);
    cudaFuncSetAttribute(oproj_kernel, cudaFuncAttributeMaxDynamicSharedMemorySize, GEMM_SMEM);

    prep_kernel<<<2368, 256>>>(x, Wq, Wk, Wv, Wo);
    qkv_kernel<<<dim3(BS_ / 128, 24), 256, GEMM_SMEM>>>(bq, bk, bv);
    flash_kernel<<<dim3(S_ / 128, H_, B_), 256, FLASH_SMEM>>>();
    oproj_kernel<<<dim3(BS_ / 128, E_ / 128), 256, GEMM_SMEM>>>(bo, out);
}

// round 10
// speedup vs baseline: 2.2605x; 1.0049x over previous
#include <cuda_runtime.h>
#include <cuda_fp16.h>
#include <cstdint>

#define B_ 4
#define S_ 2048
#define E_ 1024
#define H_ 16
#define D_ 64
#define BS_ (B_*S_)
#define BHSD (B_*H_*S_*D_)
#define LOG2E 1.4426950408889634f

// Scratch (device globals — no allocations allowed). All fp16.
__device__ __align__(16) __half g_qh[(size_t)BHSD];        // [b,h][s][d], pre-scaled
__device__ __align__(16) __half g_kh[(size_t)BHSD];        // [b,h][s][d]
__device__ __align__(16) __half g_vh[(size_t)BHSD];        // [b,h][s][d]
__device__ __align__(16) __half g_ctxh[(size_t)BS_*E_];    // [s][h*d]
__device__ __align__(16) __half g_xh[(size_t)BS_*E_];      // [s][e]
__device__ __align__(16) __half g_Wqh[H_*E_*D_];           // [h][d][e]
__device__ __align__(16) __half g_Wkh[H_*E_*D_];           // [h][d][e]
__device__ __align__(16) __half g_Wvh[H_*E_*D_];           // [h][d][e]
__device__ __align__(16) __half g_Woh[H_*D_*E_];           // [n][k]

// ---------------------------------------------------------------------------
__device__ __forceinline__ unsigned pack2h(float a, float b) {
    __half2 h = __floats2half2_rn(a, b);
    return *(unsigned*)&h;
}
__device__ __forceinline__ void mma_h(float* c, const unsigned* a, const unsigned* b) {
    asm volatile(
        "mma.sync.aligned.m16n8k16.row.col.f32.f16.f16.f32 "
        "{%0,%1,%2,%3}, {%4,%5,%6,%7}, {%8,%9}, {%0,%1,%2,%3};\n"
        : "+f"(c[0]), "+f"(c[1]), "+f"(c[2]), "+f"(c[3])
        : "r"(a[0]), "r"(a[1]), "r"(a[2]), "r"(a[3]), "r"(b[0]), "r"(b[1]));
}
__device__ __forceinline__ void ldsm4(unsigned* r, uint32_t a) {
    asm volatile("ldmatrix.sync.aligned.m8n8.x4.shared.b16 {%0,%1,%2,%3}, [%4];"
        : "=r"(r[0]), "=r"(r[1]), "=r"(r[2]), "=r"(r[3]) : "r"(a));
}
__device__ __forceinline__ void ldsm4t(unsigned* r, uint32_t a) {
    asm volatile("ldmatrix.sync.aligned.m8n8.x4.trans.shared.b16 {%0,%1,%2,%3}, [%4];"
        : "=r"(r[0]), "=r"(r[1]), "=r"(r[2]), "=r"(r[3]) : "r"(a));
}
__device__ __forceinline__ void cp16(uint32_t d, const __half* s) {
    asm volatile("cp.async.cg.shared.global [%0], [%1], 16;\n" :: "r"(d), "l"(s));
}
__device__ __forceinline__ void cp_commit() { asm volatile("cp.async.commit_group;\n"); }
__device__ __forceinline__ void cp_wait0()  { asm volatile("cp.async.wait_group 0;\n" ::: "memory"); }

// ---------------------------------------------------------------------------
// prep: fp16-convert x; transpose+convert Wq/Wk/Wv -> [h][d][e]; Wo -> [n][k]
// ---------------------------------------------------------------------------
#define N4_X  (BS_*E_/4)
#define N4_W  (H_*E_*D_/4)
#define N4_TOT (N4_X + 4*N4_W)

__global__ void prep_kernel(const float* __restrict__ x,
                            const float* __restrict__ Wq, const float* __restrict__ Wk,
                            const float* __restrict__ Wv, const float* __restrict__ Wo)
{
    int i = blockIdx.x * blockDim.x + threadIdx.x;
    int stride = gridDim.x * blockDim.x;
    for (; i < N4_TOT; i += stride) {
        if (i < N4_X) {
            float4 v = ((const float4*)x)[i];
            ((uint2*)g_xh)[i] = make_uint2(pack2h(v.x, v.y), pack2h(v.z, v.w));
        } else if (i < N4_X + 3 * N4_W) {
            int tt = i - N4_X;
            int wsel = tt / N4_W, o4 = tt % N4_W;
            const float* W = (wsel == 0) ? Wq : (wsel == 1) ? Wk : Wv;
            __half* dst = (wsel == 0) ? g_Wqh : (wsel == 1) ? g_Wkh : g_Wvh;
            int o = o4 * 4;
            int e = o & (E_ - 1);
            int rest = o >> 10;
            int d = rest & (D_ - 1);
            int hh = rest >> 6;
            const float* src = W + (size_t)hh * E_ * D_ + d;
            float v0 = src[(size_t)(e + 0) * D_];
            float v1 = src[(size_t)(e + 1) * D_];
            float v2 = src[(size_t)(e + 2) * D_];
            float v3 = src[(size_t)(e + 3) * D_];
            ((uint2*)dst)[o4] = make_uint2(pack2h(v0, v1), pack2h(v2, v3));
        } else {
            int o4 = i - N4_X - 3 * N4_W;
            int o = o4 * 4;
            int k = o & 1023;
            int n = o >> 10;
            float v0 = Wo[(size_t)(k + 0) * E_ + n];
            float v1 = Wo[(size_t)(k + 1) * E_ + n];
            float v2 = Wo[(size_t)(k + 2) * E_ + n];
            float v3 = Wo[(size_t)(k + 3) * E_ + n];
            ((uint2*)g_Woh)[o4] = make_uint2(pack2h(v0, v1), pack2h(v2, v3));
        }
    }
}

// ---------------------------------------------------------------------------
// GEMM skeleton: CTA tile 128x128, K-tile 64, 2-stage ring, 128 thr / 4 warps
// (2x2: warp tile 64x64 -> 128 acc regs/thread). Row stride 72 halves (144B).
// ---------------------------------------------------------------------------
#define GEMM_SMEM 73728
#define A_STB(s) ((uint32_t)(s) * 18432u)
#define B_STB(s) (36864u + (uint32_t)(s) * 18432u)

__device__ __forceinline__ void gemm_tile64(float c[4][8][4], uint32_t aB, uint32_t bB,
                                            int wm, int wn, int lane)
{
    const int i8  = lane & 7;
    const int sel = lane >> 3;
    const int arow_off = (sel & 1) * 8 + i8;
    const int akof     = (sel >> 1) * 8;
    const int bfsel    = sel >> 1;
    const int bkof     = (sel & 1) * 8;
    #pragma unroll
    for (int ks = 0; ks < 4; ks++) {
        unsigned a[4][4];
        #pragma unroll
        for (int mi = 0; mi < 4; mi++) {
            const int row = wm * 64 + mi * 16 + arow_off;
            ldsm4(a[mi], aB + (uint32_t)(row * 144 + (ks * 16 + akof) * 2));
        }
        unsigned bq[4][4];
        #pragma unroll
        for (int j = 0; j < 4; j++) {
            const int row = wn * 64 + (2 * j + bfsel) * 8 + i8;
            ldsm4(bq[j], bB + (uint32_t)(row * 144 + (ks * 16 + bkof) * 2));
        }
        #pragma unroll
        for (int mi = 0; mi < 4; mi++)
            #pragma unroll
            for (int j = 0; j < 4; j++) {
                mma_h(c[mi][2 * j],     a[mi], bq[j]);
                mma_h(c[mi][2 * j + 1], a[mi], bq[j] + 2);
            }
    }
}

// ---------------------------------------------------------------------------
// Kernel 1: fused QKV projection. grid (64, 24), 128 threads, 2 CTA/SM.
// ---------------------------------------------------------------------------
__global__ __launch_bounds__(128, 2) void qkv_kernel(
    const float* __restrict__ bq, const float* __restrict__ bk, const float* __restrict__ bv)
{
    extern __shared__ char smc[];
    const int tid  = threadIdx.x;
    const int m0   = blockIdx.x * 128;
    const int p0   = blockIdx.y * 2;
    const int lane = tid & 31, wid = tid >> 5;
    const int wm   = wid >> 1, wn = wid & 1;
    const int g    = lane >> 2, t = lane & 3;
    const uint32_t smb = (uint32_t)__cvta_generic_to_shared(smc);

    // cp.async mapping: 1024 16B-chunks per operand per tile; 8 per thread
    const int r0 = tid >> 3, cpos = tid & 7;
    const uint32_t sOff = (uint32_t)(r0 * 144 + cpos * 16);
    const __half* aBase = g_xh + (size_t)(m0 + r0) * E_ + cpos * 8;
    const int opA = p0 >> 4,        hhA = p0 & 15;
    const int opB = (p0 + 1) >> 4,  hhB = (p0 + 1) & 15;
    const __half* tabA = (opA == 0) ? g_Wqh : (opA == 1) ? g_Wkh : g_Wvh;
    const __half* tabB = (opB == 0) ? g_Wqh : (opB == 1) ? g_Wkh : g_Wvh;
    const __half* bBase0 = tabA + ((size_t)hhA * D_ + r0) * E_ + cpos * 8;
    const __half* bBase1 = tabB + ((size_t)hhB * D_ + r0) * E_ + cpos * 8;

    // prologue: tile 0 -> stage 0
    #pragma unroll
    for (int i = 0; i < 8; i++) {
        cp16(smb + A_STB(0) + sOff + (uint32_t)i * 2304u, aBase + (size_t)i * 16 * E_);
        const __half* bs = (i < 4) ? (bBase0 + (size_t)i * 16 * E_)
                                   : (bBase1 + (size_t)(i - 4) * 16 * E_);
        cp16(smb + B_STB(0) + sOff + (uint32_t)i * 2304u, bs);
    }
    cp_commit();

    float c[4][8][4];
    #pragma unroll
    for (int mi = 0; mi < 4; mi++)
        #pragma unroll
        for (int f = 0; f < 8; f++)
            #pragma unroll
            for (int r = 0; r < 4; r++) c[mi][f][r] = 0.f;

    for (int kt = 0; kt < 16; kt++) {
        cp_wait0();
        __syncthreads();
        if (kt + 1 < 16) {
            const uint32_t s = (uint32_t)((kt + 1) & 1);
            const int kc = (kt + 1) * 64;
            #pragma unroll
            for (int i = 0; i < 8; i++) {
                cp16(smb + A_STB(s) + sOff + (uint32_t)i * 2304u,
                     aBase + (size_t)i * 16 * E_ + kc);
                const __half* bs = (i < 4) ? (bBase0 + (size_t)i * 16 * E_ + kc)
                                           : (bBase1 + (size_t)(i - 4) * 16 * E_ + kc);
                cp16(smb + B_STB(s) + sOff + (uint32_t)i * 2304u, bs);
            }
            cp_commit();
        }
        gemm_tile64(c, smb + A_STB(kt & 1), smb + B_STB(kt & 1), wm, wn, lane);
    }

    // epilogue: bias, scale Q, fp16-round, coalesced store
    const int p  = p0 + wn;
    const int op = p >> 4, hh = p & 15;
    const float* bb = ((op == 0) ? bq : (op == 1) ? bk : bv) + hh * D_;
    __half* outb = (op == 0) ? g_qh : (op == 1) ? g_kh : g_vh;
    const float scl = (op == 0) ? (0.125f * LOG2E) : 1.0f;

    #pragma unroll
    for (int mi = 0; mi < 4; mi++) {
        #pragma unroll
        for (int rr = 0; rr < 2; rr++) {
            const int gr = m0 + wm * 64 + mi * 16 + g + rr * 8;
            const int bbi = gr >> 11, ssi = gr & 2047;
            __half* ob = outb + (((size_t)bbi * H_ + hh) * S_ + ssi) * D_;
            #pragma unroll
            for (int f = 0; f < 8; f++) {
                const int col = f * 8 + t * 2;
                float v0 = (c[mi][f][rr * 2 + 0] + bb[col])     * scl;
                float v1 = (c[mi][f][rr * 2 + 1] + bb[col + 1]) * scl;
                *(unsigned*)(ob + col) = pack2h(v0, v1);
            }
        }
    }
}

// ---------------------------------------------------------------------------
// Kernel 3: output projection. grid (64, 8), 128 threads, 2 CTA/SM.
// ---------------------------------------------------------------------------
__global__ __launch_bounds__(128, 2) void oproj_kernel(
    const float* __restrict__ bo, float* __restrict__ out)
{
    extern __shared__ char smc[];
    const int tid  = threadIdx.x;
    const int m0   = blockIdx.x * 128;
    const int n0   = blockIdx.y * 128;
    const int lane = tid & 31, wid = tid >> 5;
    const int wm   = wid >> 1, wn = wid & 1;
    const int g    = lane >> 2, t = lane & 3;
    const uint32_t smb = (uint32_t)__cvta_generic_to_shared(smc);

    const int r0 = tid >> 3, cpos = tid & 7;
    const uint32_t sOff = (uint32_t)(r0 * 144 + cpos * 16);
    const __half* aBase = g_ctxh + (size_t)(m0 + r0) * E_ + cpos * 8;
    const __half* bBase = g_Woh + (size_t)(n0 + r0) * E_ + cpos * 8;

    #pragma unroll
    for (int i = 0; i < 8; i++) {
        cp16(smb + A_STB(0) + sOff + (uint32_t)i * 2304u, aBase + (size_t)i * 16 * E_);
        cp16(smb + B_STB(0) + sOff + (uint32_t)i * 2304u, bBase + (size_t)i * 16 * E_);
    }
    cp_commit();

    float c[4][8][4];
    #pragma unroll
    for (int mi = 0; mi < 4; mi++)
        #pragma unroll
        for (int f = 0; f < 8; f++)
            #pragma unroll
            for (int r = 0; r < 4; r++) c[mi][f][r] = 0.f;

    for (int kt = 0; kt < 16; kt++) {
        cp_wait0();
        __syncthreads();
        if (kt + 1 < 16) {
            const uint32_t s = (uint32_t)((kt + 1) & 1);
            const int kc = (kt + 1) * 64;
            #pragma unroll
            for (int i = 0; i < 8; i++) {
                cp16(smb + A_STB(s) + sOff + (uint32_t)i * 2304u,
                     aBase + (size_t)i * 16 * E_ + kc);
                cp16(smb + B_STB(s) + sOff + (uint32_t)i * 2304u,
                     bBase + (size_t)i * 16 * E_ + kc);
            }
            cp_commit();
        }
        gemm_tile64(c, smb + A_STB(kt & 1), smb + B_STB(kt & 1), wm, wn, lane);
    }

    #pragma unroll
    for (int mi = 0; mi < 4; mi++) {
        const int row = m0 + wm * 64 + mi * 16 + g;
        #pragma unroll
        for (int f = 0; f < 8; f++) {
            const int col = n0 + wn * 64 + f * 8 + t * 2;
            const float b0v = bo[col], b1v = bo[col + 1];
            float2 v0; v0.x = c[mi][f][0] + b0v; v0.y = c[mi][f][1] + b1v;
            *(float2*)(out + (size_t)row * E_ + col) = v0;
            float2 v1; v1.x = c[mi][f][2] + b0v; v1.y = c[mi][f][3] + b1v;
            *(float2*)(out + (size_t)(row + 8) * E_ + col) = v1;
        }
    }
}

// ---------------------------------------------------------------------------
// Kernel 2: causal flash attention. 128 thr / 4 warps (warp = 32 q-rows),
// Bq=128, Bkv=64, 2 CTA/SM. ldmatrix (+trans V), register-P.
// smem rows 144B: Q[128]@0 | K 2x[64]@18432 | V 2x[64]@36864.
// ---------------------------------------------------------------------------
#define FLASH_SMEM 55296
#define FK_STB(s) (18432u + (uint32_t)(s) * 9216u)
#define FV_STB(s) (36864u + (uint32_t)(s) * 9216u)

__global__ __launch_bounds__(128, 2) void flash_kernel()
{
    extern __shared__ char smc[];
    const uint32_t smb = (uint32_t)__cvta_generic_to_shared(smc);

    const int iq = (int)(gridDim.x - 1 - blockIdx.x);   // heavy-first
    const int h = blockIdx.y, b = blockIdx.z;
    const int q0 = iq * 128;
    const size_t head = ((size_t)b * H_ + h) * S_ * D_;
    const __half* Qg = g_qh + head;
    const __half* Kg = g_kh + head;
    const __half* Vg = g_vh + head;

    const int tid  = threadIdx.x;
    const int lane = tid & 31, wid = tid >> 5;
    const int g    = lane >> 2, t = lane & 3;
    const int i8   = lane & 7, sel = lane >> 3;
    const int bfsel = sel >> 1;
    const int bkof  = (sel & 1) * 8;

    const int r0 = tid >> 3, cpos = tid & 7;
    const uint32_t sOff = (uint32_t)(r0 * 144 + cpos * 16);
    const __half* kBaseG = Kg + (size_t)r0 * D_ + cpos * 8;
    const ptrdiff_t v_delta = Vg - Kg;

    // prologue: Q (8 chunks/thread) + K/V tile 0 (4 chunks/thread each)
    #pragma unroll
    for (int i = 0; i < 8; i++)
        cp16(smb + sOff + (uint32_t)i * 2304u,
             Qg + (size_t)(q0 + r0 + i * 16) * D_ + cpos * 8);
    #pragma unroll
    for (int i = 0; i < 4; i++) {
        cp16(smb + FK_STB(0) + sOff + (uint32_t)i * 2304u, kBaseG + (size_t)i * 16 * D_);
        cp16(smb + FV_STB(0) + sOff + (uint32_t)i * 2304u, kBaseG + v_delta + (size_t)i * 16 * D_);
    }
    cp_commit();
    cp_wait0();
    __syncthreads();

    // Q fragments via ldmatrix (warp-private 32 rows, 2 m16-tiles)
    unsigned aQ[2][4][4];
    {
        const int kof = (sel >> 1) * 8;
        #pragma unroll
        for (int mi = 0; mi < 2; mi++) {
            const int row = wid * 32 + mi * 16 + (sel & 1) * 8 + i8;
            #pragma unroll
            for (int kk = 0; kk < 4; kk++)
                ldsm4(aQ[mi][kk], smb + (uint32_t)(row * 144 + (kk * 16 + kof) * 2));
        }
    }

    float cO[2][8][4];
    #pragma unroll
    for (int mi = 0; mi < 2; mi++)
        #pragma unroll
        for (int f = 0; f < 8; f++)
            #pragma unroll
            for (int r = 0; r < 4; r++) cO[mi][f][r] = 0.f;
    float mS[4] = {-1e30f, -1e30f, -1e30f, -1e30f};
    float lS[4] = {0.f, 0.f, 0.f, 0.f};

    const int jtmax = 2 * iq + 1;
    for (int jt = 0; jt <= jtmax; jt++) {
        if (jt > 0) {
            cp_wait0();
            __syncthreads();
        }
        if (jt < jtmax) {
            const uint32_t st = (uint32_t)((jt + 1) & 1);
            const size_t src = (size_t)(jt + 1) * 4096;
            #pragma unroll
            for (int i = 0; i < 4; i++) {
                cp16(smb + FK_STB(st) + sOff + (uint32_t)i * 2304u,
                     kBaseG + src + (size_t)i * 16 * D_);
                cp16(smb + FV_STB(st) + sOff + (uint32_t)i * 2304u,
                     kBaseG + v_delta + src + (size_t)i * 16 * D_);
            }
            cp_commit();
        }
        const uint32_t kBase = smb + FK_STB(jt & 1);
        const uint32_t vBase = smb + FV_STB(jt & 1);
        const int k0 = jt * 64;

        // S = Q K^T
        float cS[2][8][4];
        #pragma unroll
        for (int mi = 0; mi < 2; mi++)
            #pragma unroll
            for (int f = 0; f < 8; f++)
                #pragma unroll
                for (int r = 0; r < 4; r++) cS[mi][f][r] = 0.f;
        #pragma unroll
        for (int kk = 0; kk < 4; kk++) {
            #pragma unroll
            for (int j = 0; j < 4; j++) {
                unsigned bq[4];
                const int row = (2 * j + bfsel) * 8 + i8;
                ldsm4(bq, kBase + (uint32_t)(row * 144 + (kk * 16 + bkof) * 2));
                #pragma unroll
                for (int mi = 0; mi < 2; mi++) {
                    mma_h(cS[mi][2 * j],     aQ[mi][kk], bq);
                    mma_h(cS[mi][2 * j + 1], aQ[mi][kk], bq + 2);
                }
            }
        }

        // causal mask (diagonal-crossing tiles only)
        if (jt >= 2 * iq) {
            #pragma unroll
            for (int mi = 0; mi < 2; mi++) {
                const int ra = q0 + wid * 32 + mi * 16 + g, rb = ra + 8;
                #pragma unroll
                for (int f = 0; f < 8; f++) {
                    const int col = k0 + f * 8 + t * 2;
                    if (col     > ra) cS[mi][f][0] = -1e30f;
                    if (col + 1 > ra) cS[mi][f][1] = -1e30f;
                    if (col     > rb) cS[mi][f][2] = -1e30f;
                    if (col + 1 > rb) cS[mi][f][3] = -1e30f;
                }
            }
        }

        // online softmax (exp2 domain; Q pre-scaled by 0.125*log2e)
        #pragma unroll
        for (int mi = 0; mi < 2; mi++) {
            float rm0 = -1e30f, rm1 = -1e30f;
            #pragma unroll
            for (int f = 0; f < 8; f++) {
                rm0 = fmaxf(rm0, fmaxf(cS[mi][f][0], cS[mi][f][1]));
                rm1 = fmaxf(rm1, fmaxf(cS[mi][f][2], cS[mi][f][3]));
            }
            rm0 = fmaxf(rm0, __shfl_xor_sync(0xffffffffu, rm0, 1));
            rm0 = fmaxf(rm0, __shfl_xor_sync(0xffffffffu, rm0, 2));
            rm1 = fmaxf(rm1, __shfl_xor_sync(0xffffffffu, rm1, 1));
            rm1 = fmaxf(rm1, __shfl_xor_sync(0xffffffffu, rm1, 2));

            const float nm0 = fmaxf(mS[mi * 2],     rm0);
            const float nm1 = fmaxf(mS[mi * 2 + 1], rm1);
            const float corr0 = exp2f(mS[mi * 2]     - nm0);
            const float corr1 = exp2f(mS[mi * 2 + 1] - nm1);
            mS[mi * 2] = nm0; mS[mi * 2 + 1] = nm1;

            float rs0 = 0.f, rs1 = 0.f;
            #pragma unroll
            for (int f = 0; f < 8; f++) {
                cS[mi][f][0] = exp2f(cS[mi][f][0] - nm0);
                cS[mi][f][1] = exp2f(cS[mi][f][1] - nm0);
                cS[mi][f][2] = exp2f(cS[mi][f][2] - nm1);
                cS[mi][f][3] = exp2f(cS[mi][f][3] - nm1);
                rs0 += cS[mi][f][0] + cS[mi][f][1];
                rs1 += cS[mi][f][2] + cS[mi][f][3];
            }
            rs0 += __shfl_xor_sync(0xffffffffu, rs0, 1);
            rs0 += __shfl_xor_sync(0xffffffffu, rs0, 2);
            rs1 += __shfl_xor_sync(0xffffffffu, rs1, 1);
            rs1 += __shfl_xor_sync(0xffffffffu, rs1, 2);
            lS[mi * 2]     = lS[mi * 2]     * corr0 + rs0;
            lS[mi * 2 + 1] = lS[mi * 2 + 1] * corr1 + rs1;
            #pragma unroll
            for (int f = 0; f < 8; f++) {
                cO[mi][f][0] *= corr0; cO[mi][f][1] *= corr0;
                cO[mi][f][2] *= corr1; cO[mi][f][3] *= corr1;
            }
        }

        // O += P V : P packed from accumulators; V [key][d] via ldmatrix.trans
        #pragma unroll
        for (int kk = 0; kk < 4; kk++) {
            unsigned aP[2][4];
            #pragma unroll
            for (int mi = 0; mi < 2; mi++) {
                aP[mi][0] = pack2h(cS[mi][2 * kk][0],     cS[mi][2 * kk][1]);
                aP[mi][1] = pack2h(cS[mi][2 * kk][2],     cS[mi][2 * kk][3]);
                aP[mi][2] = pack2h(cS[mi][2 * kk + 1][0], cS[mi][2 * kk + 1][1]);
                aP[mi][3] = pack2h(cS[mi][2 * kk + 1][2], cS[mi][2 * kk + 1][3]);
            }
            #pragma unroll
            for (int j = 0; j < 4; j++) {
                unsigned bq[4];
                const int row = kk * 16 + (sel & 1) * 8 + i8;
                const int colb = (2 * j + (sel >> 1)) * 16;
                ldsm4t(bq, vBase + (uint32_t)(row * 144 + colb));
                #pragma unroll
                for (int mi = 0; mi < 2; mi++) {
                    mma_h(cO[mi][2 * j],     aP[mi], bq);
                    mma_h(cO[mi][2 * j + 1], aP[mi], bq + 2);
                }
            }
        }
    }

    // epilogue: normalize, fp16-round, write ctx [s][h*d]
    #pragma unroll
    for (int mi = 0; mi < 2; mi++) {
        const float inv0 = 1.0f / lS[mi * 2];
        const float inv1 = 1.0f / lS[mi * 2 + 1];
        const int q_a = q0 + wid * 32 + mi * 16 + g, q_b = q_a + 8;
        #pragma unroll
        for (int f = 0; f < 8; f++) {
            const int col = h * D_ + f * 8 + t * 2;
            *(unsigned*)(g_ctxh + ((size_t)b * S_ + q_a) * E_ + col) =
                pack2h(cO[mi][f][0] * inv0, cO[mi][f][1] * inv0);
            *(unsigned*)(g_ctxh + ((size_t)b * S_ + q_b) * E_ + col) =
                pack2h(cO[mi][f][2] * inv1, cO[mi][f][3] * inv1);
        }
    }
}

// ---------------------------------------------------------------------------
extern "C" void kernel_launch(void* const* d_in, const int* in_sizes, int n_in,
                              void* d_out, int out_size)
{
    const float* x  = (const float*)d_in[0];
    const float* Wq = (const float*)d_in[1];
    const float* Wk = (const float*)d_in[2];
    const float* Wv = (const float*)d_in[3];
    const float* bq = (const float*)d_in[4];
    const float* bk = (const float*)d_in[5];
    const float* bv = (const float*)d_in[6];
    const float* Wo = (const float*)d_in[7];
    const float* bo = (const float*)d_in[8];
    float* out = (float*)d_out;

    cudaFuncSetAttribute(qkv_kernel,   cudaFuncAttributeMaxDynamicSharedMemorySize, GEMM_SMEM);
    cudaFuncSetAttribute(flash_kernel, cudaFuncAttributeMaxDynamicSharedMemorySize, FLASH_SMEM);
    cudaFuncSetAttribute(oproj_kernel, cudaFuncAttributeMaxDynamicSharedMemorySize, GEMM_SMEM);

    prep_kernel<<<2368, 256>>>(x, Wq, Wk, Wv, Wo);
    qkv_kernel<<<dim3(BS_ / 128, 24), 128, GEMM_SMEM>>>(bq, bk, bv);
    flash_kernel<<<dim3(S_ / 128, H_, B_), 128, FLASH_SMEM>>>();
    oproj_kernel<<<dim3(BS_ / 128, E_ / 128), 128, GEMM_SMEM>>>(bo, out);
}